// round 12
// baseline (speedup 1.0000x reference)
#include <cuda_runtime.h>
#include <cuda_fp16.h>

#define NNODES 100000
#define CDIM   128
#define EDGES  3200000
#define NB_SCAN 391   // ceil(NNODES/256)

// Scratch (__device__ globals; no allocation allowed). fp16 feature plane.
__device__ __half g_xh  [(size_t)NNODES * CDIM];
__device__ __half g_h1h [(size_t)NNODES * CDIM];
__device__ __half g_h2h [(size_t)NNODES * CDIM];
__device__ __half g_th  [(size_t)NNODES * 64];    // proj cols 0..63 (fp16)
__device__ float  g_ts  [(size_t)NNODES * 64];    // proj cols 64..127 (fp32 self)
__device__ float  g_inv[NNODES];
__device__ int    g_deg[NNODES];
__device__ int    g_rowptr[NNODES + 1];
__device__ int    g_wcur[NNODES];
__device__ int    g_eidx[EDGES];
__device__ int    g_bsum[NB_SCAN];

// ---------------------------------------------------------------------------
// CSR build step 1: degree histogram
__global__ void hist_kernel(const int* __restrict__ ei, int* __restrict__ deg) {
    int e = blockIdx.x * blockDim.x + threadIdx.x;
    if (e < EDGES) atomicAdd(deg + ei[EDGES + e], 1);
}

__global__ void partial_kernel(const int* __restrict__ deg, int* __restrict__ bsum) {
    int i = blockIdx.x * 256 + threadIdx.x;
    int v = (i < NNODES) ? deg[i] : 0;
#pragma unroll
    for (int off = 16; off > 0; off >>= 1)
        v += __shfl_down_sync(0xffffffffu, v, off);
    __shared__ int ws[8];
    int wid = threadIdx.x >> 5, lane = threadIdx.x & 31;
    if (lane == 0) ws[wid] = v;
    __syncthreads();
    if (wid == 0 && lane < 8) {
        int s = ws[lane];
#pragma unroll
        for (int off = 4; off > 0; off >>= 1)
            s += __shfl_down_sync(0x000000ffu, s, off);
        if (lane == 0) bsum[blockIdx.x] = s;
    }
}

__global__ void scanb_kernel(int* __restrict__ bsum) {
    int t = threadIdx.x;
    int v = (t < NB_SCAN) ? bsum[t] : 0;
    int x = v;
#pragma unroll
    for (int off = 1; off < 32; off <<= 1) {
        int y = __shfl_up_sync(0xffffffffu, x, off);
        if ((t & 31) >= off) x += y;
    }
    __shared__ int ws[16];
    int wid = t >> 5, lane = t & 31;
    if (lane == 31) ws[wid] = x;
    __syncthreads();
    if (wid == 0 && lane < 16) {
        int s = ws[lane];
#pragma unroll
        for (int off = 1; off < 16; off <<= 1) {
            int y = __shfl_up_sync(0x0000ffffu, s, off);
            if (lane >= off) s += y;
        }
        ws[lane] = s;
    }
    __syncthreads();
    int woff = (wid > 0) ? ws[wid - 1] : 0;
    if (t < NB_SCAN) bsum[t] = woff + x - v;   // exclusive
}

__global__ void rescan_kernel(const int* __restrict__ deg, const int* __restrict__ bsum,
                              int* __restrict__ rowptr) {
    int i = blockIdx.x * 256 + threadIdx.x;
    int v = (i < NNODES) ? deg[i] : 0;
    int x = v;
#pragma unroll
    for (int off = 1; off < 32; off <<= 1) {
        int y = __shfl_up_sync(0xffffffffu, x, off);
        if ((threadIdx.x & 31) >= off) x += y;
    }
    __shared__ int ws[8];
    int wid = threadIdx.x >> 5, lane = threadIdx.x & 31;
    if (lane == 31) ws[wid] = x;
    __syncthreads();
    if (wid == 0 && lane < 8) {
        int s = ws[lane];
#pragma unroll
        for (int off = 1; off < 8; off <<= 1) {
            int y = __shfl_up_sync(0x000000ffu, s, off);
            if (lane >= off) s += y;
        }
        ws[lane] = s;
    }
    __syncthreads();
    int woff = (wid > 0) ? ws[wid - 1] : 0;
    if (i < NNODES) rowptr[i] = bsum[blockIdx.x] + woff + x - v;
}

__global__ void initcur_kernel(const int* __restrict__ rowptr, const int* __restrict__ deg,
                               int* __restrict__ wcur, float* __restrict__ inv,
                               int* __restrict__ rowptr_end) {
    int n = blockIdx.x * blockDim.x + threadIdx.x;
    if (n == 0) *rowptr_end = EDGES;
    if (n < NNODES) {
        wcur[n] = rowptr[n];
        inv[n]  = 1.0f / fmaxf((float)deg[n], 1.0f);
    }
}

__global__ void fill_kernel(const int* __restrict__ ei, int* __restrict__ wcur,
                            int* __restrict__ eidx) {
    int e = blockIdx.x * blockDim.x + threadIdx.x;
    if (e < EDGES) {
        int src = ei[e];
        int dst = ei[EDGES + e];
        int pos = atomicAdd(wcur + dst, 1);
        eidx[pos] = src;
    }
}

// ---------------------------------------------------------------------------
// fp32 -> fp16 for x (once)
__global__ void tohalf_kernel(const float* __restrict__ in, __half* __restrict__ out) {
    long long i = (long long)blockIdx.x * blockDim.x + threadIdx.x;
    long long total = (long long)NNODES * CDIM / 8;
    if (i >= total) return;
    const float4* p = (const float4*)(in + i * 8);
    float4 a = p[0], b = p[1];
    __half2 h0 = __float22half2_rn(make_float2(a.x, a.y));
    __half2 h1 = __float22half2_rn(make_float2(a.z, a.w));
    __half2 h2 = __float22half2_rn(make_float2(b.x, b.y));
    __half2 h3 = __float22half2_rn(make_float2(b.z, b.w));
    uint4 v;
    v.x = *(unsigned*)&h0; v.y = *(unsigned*)&h1;
    v.z = *(unsigned*)&h2; v.w = *(unsigned*)&h3;
    *(uint4*)(out + i * 8) = v;
}

// ---------------------------------------------------------------------------
#define MMA_16816(c, a, b) \
    asm volatile("mma.sync.aligned.m16n8k16.row.col.f32.f16.f16.f32 " \
        "{%0,%1,%2,%3}, {%4,%5,%6,%7}, {%8,%9}, {%0,%1,%2,%3};" \
        : "+f"((c)[0]), "+f"((c)[1]), "+f"((c)[2]), "+f"((c)[3]) \
        : "r"((a)[0]), "r"((a)[1]), "r"((a)[2]), "r"((a)[3]), \
          "r"((b)[0]), "r"((b)[1]))

__device__ __forceinline__ uint4 f8h8(float4 f0, float4 f1) {
    __half2 h0 = __float22half2_rn(make_float2(f0.x, f0.y));
    __half2 h1 = __float22half2_rn(make_float2(f0.z, f0.w));
    __half2 h2 = __float22half2_rn(make_float2(f1.x, f1.y));
    __half2 h3 = __float22half2_rn(make_float2(f1.z, f1.w));
    uint4 v;
    v.x = *(unsigned*)&h0; v.y = *(unsigned*)&h1;
    v.z = *(unsigned*)&h2; v.w = *(unsigned*)&h3;
    return v;
}

#define TILE_LD 136    // halves per tile row (272B = 17*16B, ldmatrix-aligned)
#define SMEM_BYTES ((128 * TILE_LD + 128 * 72) * 2)

// ---------------------------------------------------------------------------
// FUSED layer kernel: per block of 128 nodes —
//   phase A: gather-mean (fp16 in, fp32 acc) directly into smem tile
//   phase 0: tile @ Wl^T (MMA)
//   phase B: reload tile with self rows (coalesced)
//   phase 1: tile @ Wr^T (MMA), epilogue bias+relu -> fp16 out
__global__ __launch_bounds__(256)
void layer_tc(const int* __restrict__ rowptr, const int* __restrict__ eidx,
              const __half* __restrict__ hh, const float* __restrict__ inv,
              const float* __restrict__ Wl, const float* __restrict__ bl,
              const float* __restrict__ Wr, __half* __restrict__ outh) {
    extern __shared__ __half sm[];
    __half (*tile)[TILE_LD] = (__half(*)[TILE_LD])sm;           // 128 x 136
    __half (*Bs)[72]        = (__half(*)[72])(sm + 128 * TILE_LD);

    const int tid = threadIdx.x, wid = tid >> 5, lane = tid & 31;
    const int m0 = blockIdx.x * 128;
    const int wm = (wid & 3) * 32;
    const int wn = (wid >> 2) * 64;

    // ---- phase A: gather-mean into tile (warp per node, 16 nodes/warp) ----
    for (int r = 0; r < 16; r++) {
        int m = wid * 16 + r;
        int node = m0 + m;
        float acc[4] = {0.f, 0.f, 0.f, 0.f};
        if (node < NNODES) {
            int s = rowptr[node], e = rowptr[node + 1];
            int i = s;
            for (; i + 7 < e; i += 8) {             // 8 outstanding loads
                uint2 u0 = *(const uint2*)(hh + (size_t)eidx[i+0] * 128 + lane * 4);
                uint2 u1 = *(const uint2*)(hh + (size_t)eidx[i+1] * 128 + lane * 4);
                uint2 u2 = *(const uint2*)(hh + (size_t)eidx[i+2] * 128 + lane * 4);
                uint2 u3 = *(const uint2*)(hh + (size_t)eidx[i+3] * 128 + lane * 4);
                uint2 u4 = *(const uint2*)(hh + (size_t)eidx[i+4] * 128 + lane * 4);
                uint2 u5 = *(const uint2*)(hh + (size_t)eidx[i+5] * 128 + lane * 4);
                uint2 u6 = *(const uint2*)(hh + (size_t)eidx[i+6] * 128 + lane * 4);
                uint2 u7 = *(const uint2*)(hh + (size_t)eidx[i+7] * 128 + lane * 4);
                float2 a, b;
                a = __half22float2(*(__half2*)&u0.x); acc[0]+=a.x; acc[1]+=a.y;
                b = __half22float2(*(__half2*)&u0.y); acc[2]+=b.x; acc[3]+=b.y;
                a = __half22float2(*(__half2*)&u1.x); acc[0]+=a.x; acc[1]+=a.y;
                b = __half22float2(*(__half2*)&u1.y); acc[2]+=b.x; acc[3]+=b.y;
                a = __half22float2(*(__half2*)&u2.x); acc[0]+=a.x; acc[1]+=a.y;
                b = __half22float2(*(__half2*)&u2.y); acc[2]+=b.x; acc[3]+=b.y;
                a = __half22float2(*(__half2*)&u3.x); acc[0]+=a.x; acc[1]+=a.y;
                b = __half22float2(*(__half2*)&u3.y); acc[2]+=b.x; acc[3]+=b.y;
                a = __half22float2(*(__half2*)&u4.x); acc[0]+=a.x; acc[1]+=a.y;
                b = __half22float2(*(__half2*)&u4.y); acc[2]+=b.x; acc[3]+=b.y;
                a = __half22float2(*(__half2*)&u5.x); acc[0]+=a.x; acc[1]+=a.y;
                b = __half22float2(*(__half2*)&u5.y); acc[2]+=b.x; acc[3]+=b.y;
                a = __half22float2(*(__half2*)&u6.x); acc[0]+=a.x; acc[1]+=a.y;
                b = __half22float2(*(__half2*)&u6.y); acc[2]+=b.x; acc[3]+=b.y;
                a = __half22float2(*(__half2*)&u7.x); acc[0]+=a.x; acc[1]+=a.y;
                b = __half22float2(*(__half2*)&u7.y); acc[2]+=b.x; acc[3]+=b.y;
            }
            for (; i < e; i++) {
                uint2 u0 = *(const uint2*)(hh + (size_t)eidx[i] * 128 + lane * 4);
                float2 a = __half22float2(*(__half2*)&u0.x);
                float2 b = __half22float2(*(__half2*)&u0.y);
                acc[0]+=a.x; acc[1]+=a.y; acc[2]+=b.x; acc[3]+=b.y;
            }
            float iv = inv[node];
            acc[0]*=iv; acc[1]*=iv; acc[2]*=iv; acc[3]*=iv;
        }
        __half2 p0 = __float22half2_rn(make_float2(acc[0], acc[1]));
        __half2 p1 = __float22half2_rn(make_float2(acc[2], acc[3]));
        uint2 st; st.x = *(unsigned*)&p0; st.y = *(unsigned*)&p1;
        *(uint2*)&tile[m][lane * 4] = st;
    }

    float acc[2][8][4];
#pragma unroll
    for (int i = 0; i < 2; i++)
#pragma unroll
        for (int j = 0; j < 8; j++)
#pragma unroll
            for (int d = 0; d < 4; d++) acc[i][j][d] = 0.f;

#pragma unroll
    for (int phase = 0; phase < 2; phase++) {
        if (phase == 1) {
            __syncthreads();     // all phase-0 MMA reads done
            // reload tile with self rows (coalesced uint4)
#pragma unroll
            for (int s = tid; s < 128 * 16; s += 256) {
                int m = s >> 4, kg = (s & 15) * 8;
                uint4 v = make_uint4(0, 0, 0, 0);
                int node = m0 + m;
                if (node < NNODES)
                    v = *(const uint4*)(hh + (size_t)node * CDIM + kg);
                *(uint4*)&tile[m][kg] = v;
            }
        }
        const float* B = phase ? Wr : Wl;
#pragma unroll
        for (int kc = 0; kc < CDIM; kc += 64) {
            __syncthreads();
#pragma unroll
            for (int s = tid; s < 128 * 8; s += 256) {
                int c = s >> 3, kg = (s & 7) * 8;
                const float4* p = (const float4*)(B + (size_t)c * CDIM + kc + kg);
                *(uint4*)&Bs[c][kg] = f8h8(p[0], p[1]);
            }
            __syncthreads();
#pragma unroll
            for (int ks = 0; ks < 4; ks++) {
                int k0 = ks * 16;
                unsigned a[2][4];
#pragma unroll
                for (int mf = 0; mf < 2; mf++) {
                    int row = wm + mf * 16 + (lane & 15);
                    int col = kc + k0 + ((lane >> 4) << 3);
                    unsigned addr = (unsigned)__cvta_generic_to_shared(&tile[row][col]);
                    asm volatile("ldmatrix.sync.aligned.m8n8.x4.shared.b16 {%0,%1,%2,%3}, [%4];"
                        : "=r"(a[mf][0]), "=r"(a[mf][1]), "=r"(a[mf][2]), "=r"(a[mf][3])
                        : "r"(addr));
                }
#pragma unroll
                for (int nf = 0; nf < 8; nf++) {
                    int l = lane & 15;
                    int rown = wn + nf * 8 + (l & 7);
                    int col = k0 + ((l >> 3) << 3);
                    unsigned addr = (unsigned)__cvta_generic_to_shared(&Bs[rown][col]);
                    unsigned b[2];
                    asm volatile("ldmatrix.sync.aligned.m8n8.x2.shared.b16 {%0,%1}, [%2];"
                        : "=r"(b[0]), "=r"(b[1]) : "r"(addr));
                    MMA_16816(acc[0][nf], a[0], b);
                    MMA_16816(acc[1][nf], a[1], b);
                }
            }
        }
    }

    const int tg = lane >> 2;
    const int tc = (lane & 3) * 2;
#pragma unroll
    for (int mf = 0; mf < 2; mf++) {
#pragma unroll
        for (int nf = 0; nf < 8; nf++) {
            int n_ = wn + nf * 8 + tc;
            float b0 = bl[n_], b1 = bl[n_ + 1];
            int mA = m0 + wm + mf * 16 + tg;
            int mB = mA + 8;
            if (mA < NNODES) {
                __half2 hv = __float22half2_rn(make_float2(
                    fmaxf(acc[mf][nf][0] + b0, 0.f), fmaxf(acc[mf][nf][1] + b1, 0.f)));
                *(__half2*)(outh + (size_t)mA * 128 + n_) = hv;
            }
            if (mB < NNODES) {
                __half2 hv = __float22half2_rn(make_float2(
                    fmaxf(acc[mf][nf][2] + b0, 0.f), fmaxf(acc[mf][nf][3] + b1, 0.f)));
                *(__half2*)(outh + (size_t)mB * 128 + n_) = hv;
            }
        }
    }
}

// ---------------------------------------------------------------------------
// proj: cols 0..63 = h@Wl3^T -> th (fp16); cols 64..127 = h@Wr3^T -> ts (fp32)
__global__ __launch_bounds__(256)
void proj_tc(const __half* __restrict__ h,
             const float* __restrict__ Wl, const float* __restrict__ Wr,
             __half* __restrict__ th, float* __restrict__ ts) {
    constexpr int BM = 128, BN = 128, BK = 64, LD = 72;
    __shared__ __half As[BM][LD];
    __shared__ __half Bs[BN][LD];

    const int tid = threadIdx.x, wid = tid >> 5, lane = tid & 31;
    const int m0 = blockIdx.x * BM;
    const int wm = (wid & 3) * 32;
    const int wn = (wid >> 2) * 64;

    float acc[2][8][4];
#pragma unroll
    for (int i = 0; i < 2; i++)
#pragma unroll
        for (int j = 0; j < 8; j++)
#pragma unroll
            for (int d = 0; d < 4; d++) acc[i][j][d] = 0.f;

#pragma unroll
    for (int kc = 0; kc < CDIM; kc += BK) {
        __syncthreads();
#pragma unroll
        for (int s = tid; s < BM * BK / 8; s += 256) {
            int m = s >> 3, kg = (s & 7) * 8;
            uint4 v = make_uint4(0, 0, 0, 0);
            int node = m0 + m;
            if (node < NNODES)
                v = *(const uint4*)(h + (size_t)node * CDIM + kc + kg);
            *(uint4*)&As[m][kg] = v;
        }
#pragma unroll
        for (int s = tid; s < BN * BK / 8; s += 256) {
            int c = s >> 3, kg = (s & 7) * 8;
            const float* w = (c < 64) ? (Wl + (size_t)c * CDIM)
                                      : (Wr + (size_t)(c - 64) * CDIM);
            const float4* p = (const float4*)(w + kc + kg);
            *(uint4*)&Bs[c][kg] = f8h8(p[0], p[1]);
        }
        __syncthreads();

#pragma unroll
        for (int ks = 0; ks < 4; ks++) {
            int k0 = ks * 16;
            unsigned a[2][4];
#pragma unroll
            for (int mf = 0; mf < 2; mf++) {
                int row = wm + mf * 16 + (lane & 15);
                int col = k0 + ((lane >> 4) << 3);
                unsigned addr = (unsigned)__cvta_generic_to_shared(&As[row][col]);
                asm volatile("ldmatrix.sync.aligned.m8n8.x4.shared.b16 {%0,%1,%2,%3}, [%4];"
                    : "=r"(a[mf][0]), "=r"(a[mf][1]), "=r"(a[mf][2]), "=r"(a[mf][3])
                    : "r"(addr));
            }
#pragma unroll
            for (int nf = 0; nf < 8; nf++) {
                int l = lane & 15;
                int rown = wn + nf * 8 + (l & 7);
                int col = k0 + ((l >> 3) << 3);
                unsigned addr = (unsigned)__cvta_generic_to_shared(&Bs[rown][col]);
                unsigned b[2];
                asm volatile("ldmatrix.sync.aligned.m8n8.x2.shared.b16 {%0,%1}, [%2];"
                    : "=r"(b[0]), "=r"(b[1]) : "r"(addr));
                MMA_16816(acc[0][nf], a[0], b);
                MMA_16816(acc[1][nf], a[1], b);
            }
        }
    }

    const int tg = lane >> 2;
    const int tc = (lane & 3) * 2;
#pragma unroll
    for (int mf = 0; mf < 2; mf++) {
#pragma unroll
        for (int nf = 0; nf < 8; nf++) {
            int n_ = wn + nf * 8 + tc;
            int mA = m0 + wm + mf * 16 + tg;
            int mB = mA + 8;
            if (n_ < 64) {
                if (mA < NNODES)
                    *(__half2*)(th + (size_t)mA * 64 + n_) = __float22half2_rn(
                        make_float2(acc[mf][nf][0], acc[mf][nf][1]));
                if (mB < NNODES)
                    *(__half2*)(th + (size_t)mB * 64 + n_) = __float22half2_rn(
                        make_float2(acc[mf][nf][2], acc[mf][nf][3]));
            } else {
                int c = n_ - 64;
                if (mA < NNODES)
                    *(float2*)(ts + (size_t)mA * 64 + c) =
                        make_float2(acc[mf][nf][0], acc[mf][nf][1]);
                if (mB < NNODES)
                    *(float2*)(ts + (size_t)mB * 64 + c) =
                        make_float2(acc[mf][nf][2], acc[mf][nf][3]);
            }
        }
    }
}

// Layer-3 fused aggregate: mean(th 64-wide) + ts[n,c] + bl3[c] -> out (fp32)
__global__ void aggregate_final_kernel(const int* __restrict__ rowptr,
                                       const int* __restrict__ eidx,
                                       const __half* __restrict__ th,
                                       const float* __restrict__ ts,
                                       const float* __restrict__ bl,
                                       const float* __restrict__ inv,
                                       float* __restrict__ out) {
    int warp = (blockIdx.x * blockDim.x + threadIdx.x) >> 5;
    int lane = threadIdx.x & 31;
    if (warp >= NNODES) return;
    int s = rowptr[warp];
    int e = rowptr[warp + 1];

    float a0 = 0.f, a1 = 0.f;
    int i = s;
    for (; i + 3 < e; i += 4) {
        int s0 = eidx[i], s1 = eidx[i+1], s2 = eidx[i+2], s3 = eidx[i+3];
        unsigned u0 = *(const unsigned*)(th + (size_t)s0 * 64 + lane * 2);
        unsigned u1 = *(const unsigned*)(th + (size_t)s1 * 64 + lane * 2);
        unsigned u2 = *(const unsigned*)(th + (size_t)s2 * 64 + lane * 2);
        unsigned u3 = *(const unsigned*)(th + (size_t)s3 * 64 + lane * 2);
        float2 a;
        a = __half22float2(*(__half2*)&u0); a0 += a.x; a1 += a.y;
        a = __half22float2(*(__half2*)&u1); a0 += a.x; a1 += a.y;
        a = __half22float2(*(__half2*)&u2); a0 += a.x; a1 += a.y;
        a = __half22float2(*(__half2*)&u3); a0 += a.x; a1 += a.y;
    }
    for (; i < e; i++) {
        unsigned u0 = *(const unsigned*)(th + (size_t)eidx[i] * 64 + lane * 2);
        float2 a = __half22float2(*(__half2*)&u0);
        a0 += a.x; a1 += a.y;
    }

    float iv = inv[warp];
    float2 self = *(const float2*)(ts + (size_t)warp * 64 + lane * 2);
    float2 bb   = *(const float2*)(bl + lane * 2);
    *(float2*)(out + (size_t)warp * 64 + lane * 2) =
        make_float2(a0 * iv + self.x + bb.x, a1 * iv + self.y + bb.y);
}

// ---------------------------------------------------------------------------
extern "C" void kernel_launch(void* const* d_in, const int* in_sizes, int n_in,
                              void* d_out, int out_size) {
    const float* x   = (const float*)d_in[0];
    const int*   ei  = (const int*)d_in[1];      // int32 (JAX x64 disabled)
    const float* Wl1 = (const float*)d_in[2];
    const float* bl1 = (const float*)d_in[3];
    const float* Wr1 = (const float*)d_in[4];
    const float* Wl2 = (const float*)d_in[5];
    const float* bl2 = (const float*)d_in[6];
    const float* Wr2 = (const float*)d_in[7];
    const float* Wl3 = (const float*)d_in[8];
    const float* bl3 = (const float*)d_in[9];
    const float* Wr3 = (const float*)d_in[10];
    float* out = (float*)d_out;

    __half *xh, *h1h, *h2h, *th;
    float *ts, *inv;
    int *deg, *rowptr, *wcur, *eidx, *bsum;
    cudaGetSymbolAddress((void**)&xh,   g_xh);
    cudaGetSymbolAddress((void**)&h1h,  g_h1h);
    cudaGetSymbolAddress((void**)&h2h,  g_h2h);
    cudaGetSymbolAddress((void**)&th,   g_th);
    cudaGetSymbolAddress((void**)&ts,   g_ts);
    cudaGetSymbolAddress((void**)&inv,  g_inv);
    cudaGetSymbolAddress((void**)&deg,  g_deg);
    cudaGetSymbolAddress((void**)&rowptr, g_rowptr);
    cudaGetSymbolAddress((void**)&wcur, g_wcur);
    cudaGetSymbolAddress((void**)&eidx, g_eidx);
    cudaGetSymbolAddress((void**)&bsum, g_bsum);

    cudaFuncSetAttribute(layer_tc, cudaFuncAttributeMaxDynamicSharedMemorySize,
                         SMEM_BYTES);

    const int eBlocks = (EDGES + 255) / 256;
    const int aggBlocks = (NNODES * 32 + 255) / 256;
    const int combBlocks = (NNODES + 127) / 128;
    const int cvtBlocks = (int)(((long long)NNODES * CDIM / 8 + 255) / 256);

    // --- CSR build (once per launch) ---
    cudaMemsetAsync(deg, 0, NNODES * sizeof(int), 0);
    hist_kernel<<<eBlocks, 256>>>(ei, deg);
    partial_kernel<<<NB_SCAN, 256>>>(deg, bsum);
    scanb_kernel<<<1, 512>>>(bsum);
    rescan_kernel<<<NB_SCAN, 256>>>(deg, bsum, rowptr);
    initcur_kernel<<<NB_SCAN, 256>>>(rowptr, deg, wcur, inv, rowptr + NNODES);
    fill_kernel<<<eBlocks, 256>>>(ei, wcur, eidx);

    // --- Layer 1 (fused aggregate+GEMM): x -> h1h ---
    tohalf_kernel<<<cvtBlocks, 256>>>(x, xh);
    layer_tc<<<combBlocks, 256, SMEM_BYTES>>>(rowptr, eidx, xh, inv,
                                              Wl1, bl1, Wr1, h1h);

    // --- Layer 2 (fused): h1h -> h2h ---
    layer_tc<<<combBlocks, 256, SMEM_BYTES>>>(rowptr, eidx, h1h, inv,
                                              Wl2, bl2, Wr2, h2h);

    // --- Layer 3: proj (th fp16 / ts fp32), fused 64-wide aggregate ---
    proj_tc<<<combBlocks, 256>>>(h2h, Wl3, Wr3, th, ts);
    aggregate_final_kernel<<<aggBlocks, 256>>>(rowptr, eidx, th, ts, bl3, inv, out);
}

// round 13
// speedup vs baseline: 1.9304x; 1.9304x over previous
#include <cuda_runtime.h>
#include <cuda_fp16.h>

#define NNODES 100000
#define CDIM   128
#define EDGES  3200000
#define NB_SCAN 391   // ceil(NNODES/256)

// Scratch (__device__ globals; no allocation allowed). fp16 feature plane.
__device__ __half g_xh  [(size_t)NNODES * CDIM];
__device__ __half g_aggh[(size_t)NNODES * CDIM];
__device__ __half g_h1h [(size_t)NNODES * CDIM];
__device__ __half g_h2h [(size_t)NNODES * CDIM];
__device__ __half g_th  [(size_t)NNODES * 64];    // proj cols 0..63 (fp16)
__device__ float  g_ts  [(size_t)NNODES * 64];    // proj cols 64..127 (fp32 self)
__device__ float  g_inv[NNODES];
__device__ int    g_deg[NNODES];
__device__ int    g_rowptr[NNODES + 1];
__device__ int    g_wcur[NNODES];
__device__ int    g_eidx[EDGES];
__device__ int    g_bsum[NB_SCAN];

// ---------------------------------------------------------------------------
// CSR build step 1: degree histogram, 4 edges per thread (ILP)
__global__ void hist_kernel(const int* __restrict__ ei, int* __restrict__ deg) {
    int e4 = (blockIdx.x * blockDim.x + threadIdx.x) * 4;
    if (e4 + 3 < EDGES) {
        int4 d = *(const int4*)(ei + EDGES + e4);
        atomicAdd(deg + d.x, 1);
        atomicAdd(deg + d.y, 1);
        atomicAdd(deg + d.z, 1);
        atomicAdd(deg + d.w, 1);
    } else {
        for (int e = e4; e < EDGES; e++)
            atomicAdd(deg + ei[EDGES + e], 1);
    }
}

// step 2a: per-256-chunk partial sums
__global__ void partial_kernel(const int* __restrict__ deg, int* __restrict__ bsum) {
    int i = blockIdx.x * 256 + threadIdx.x;
    int v = (i < NNODES) ? deg[i] : 0;
#pragma unroll
    for (int off = 16; off > 0; off >>= 1)
        v += __shfl_down_sync(0xffffffffu, v, off);
    __shared__ int ws[8];
    int wid = threadIdx.x >> 5, lane = threadIdx.x & 31;
    if (lane == 0) ws[wid] = v;
    __syncthreads();
    if (wid == 0 && lane < 8) {
        int s = ws[lane];
#pragma unroll
        for (int off = 4; off > 0; off >>= 1)
            s += __shfl_down_sync(0x000000ffu, s, off);
        if (lane == 0) bsum[blockIdx.x] = s;
    }
}

// step 2b: exclusive scan of NB_SCAN block sums (single block, 512 threads)
__global__ void scanb_kernel(int* __restrict__ bsum) {
    int t = threadIdx.x;
    int v = (t < NB_SCAN) ? bsum[t] : 0;
    int x = v;
#pragma unroll
    for (int off = 1; off < 32; off <<= 1) {
        int y = __shfl_up_sync(0xffffffffu, x, off);
        if ((t & 31) >= off) x += y;
    }
    __shared__ int ws[16];
    int wid = t >> 5, lane = t & 31;
    if (lane == 31) ws[wid] = x;
    __syncthreads();
    if (wid == 0 && lane < 16) {
        int s = ws[lane];
#pragma unroll
        for (int off = 1; off < 16; off <<= 1) {
            int y = __shfl_up_sync(0x0000ffffu, s, off);
            if (lane >= off) s += y;
        }
        ws[lane] = s;
    }
    __syncthreads();
    int woff = (wid > 0) ? ws[wid - 1] : 0;
    if (t < NB_SCAN) bsum[t] = woff + x - v;   // exclusive
}

// step 2c: re-scan chunks -> rowptr; also wcur, inv, rowptr[NNODES]
__global__ void rescan_kernel(const int* __restrict__ deg, const int* __restrict__ bsum,
                              int* __restrict__ rowptr, int* __restrict__ wcur,
                              float* __restrict__ inv) {
    int i = blockIdx.x * 256 + threadIdx.x;
    int v = (i < NNODES) ? deg[i] : 0;
    int x = v;
#pragma unroll
    for (int off = 1; off < 32; off <<= 1) {
        int y = __shfl_up_sync(0xffffffffu, x, off);
        if ((threadIdx.x & 31) >= off) x += y;
    }
    __shared__ int ws[8];
    int wid = threadIdx.x >> 5, lane = threadIdx.x & 31;
    if (lane == 31) ws[wid] = x;
    __syncthreads();
    if (wid == 0 && lane < 8) {
        int s = ws[lane];
#pragma unroll
        for (int off = 1; off < 8; off <<= 1) {
            int y = __shfl_up_sync(0x000000ffu, s, off);
            if (lane >= off) s += y;
        }
        ws[lane] = s;
    }
    __syncthreads();
    int woff = (wid > 0) ? ws[wid - 1] : 0;
    if (i < NNODES) {
        int rp = bsum[blockIdx.x] + woff + x - v;
        rowptr[i] = rp;
        wcur[i]   = rp;
        inv[i]    = 1.0f / fmaxf((float)v, 1.0f);
        if (i == 0) rowptr[NNODES] = EDGES;
    }
}

// step 3: fill CSR adjacency, 4 edges per thread (ILP)
__global__ void fill_kernel(const int* __restrict__ ei, int* __restrict__ wcur,
                            int* __restrict__ eidx) {
    int e4 = (blockIdx.x * blockDim.x + threadIdx.x) * 4;
    if (e4 + 3 < EDGES) {
        int4 s = *(const int4*)(ei + e4);
        int4 d = *(const int4*)(ei + EDGES + e4);
        int p0 = atomicAdd(wcur + d.x, 1);
        int p1 = atomicAdd(wcur + d.y, 1);
        int p2 = atomicAdd(wcur + d.z, 1);
        int p3 = atomicAdd(wcur + d.w, 1);
        eidx[p0] = s.x;
        eidx[p1] = s.y;
        eidx[p2] = s.z;
        eidx[p3] = s.w;
    } else {
        for (int e = e4; e < EDGES; e++) {
            int pos = atomicAdd(wcur + ei[EDGES + e], 1);
            eidx[pos] = ei[e];
        }
    }
}

// ---------------------------------------------------------------------------
// fp32 -> fp16 for x (once)
__global__ void tohalf_kernel(const float* __restrict__ in, __half* __restrict__ out) {
    long long i = (long long)blockIdx.x * blockDim.x + threadIdx.x;
    long long total = (long long)NNODES * CDIM / 8;
    if (i >= total) return;
    const float4* p = (const float4*)(in + i * 8);
    float4 a = p[0], b = p[1];
    __half2 h0 = __float22half2_rn(make_float2(a.x, a.y));
    __half2 h1 = __float22half2_rn(make_float2(a.z, a.w));
    __half2 h2 = __float22half2_rn(make_float2(b.x, b.y));
    __half2 h3 = __float22half2_rn(make_float2(b.z, b.w));
    uint4 v;
    v.x = *(unsigned*)&h0; v.y = *(unsigned*)&h1;
    v.z = *(unsigned*)&h2; v.w = *(unsigned*)&h3;
    *(uint4*)(out + i * 8) = v;
}

// ---------------------------------------------------------------------------
// Gather-aggregate (fp16 in, fp32 accumulate, fp16 mean out): warp per node.
__global__ void aggregate128_kernel(const int* __restrict__ rowptr,
                                    const int* __restrict__ eidx,
                                    const __half* __restrict__ hh,
                                    const float* __restrict__ inv,
                                    __half* __restrict__ out) {
    int warp = (blockIdx.x * blockDim.x + threadIdx.x) >> 5;
    int lane = threadIdx.x & 31;
    if (warp >= NNODES) return;
    int s = rowptr[warp];
    int e = rowptr[warp + 1];

    float acc[4] = {0.f, 0.f, 0.f, 0.f};

    int i = s;
    for (; i + 3 < e; i += 4) {
        int s0 = eidx[i], s1 = eidx[i+1], s2 = eidx[i+2], s3 = eidx[i+3];
        uint2 u0 = *(const uint2*)(hh + (size_t)s0 * 128 + lane * 4);
        uint2 u1 = *(const uint2*)(hh + (size_t)s1 * 128 + lane * 4);
        uint2 u2 = *(const uint2*)(hh + (size_t)s2 * 128 + lane * 4);
        uint2 u3 = *(const uint2*)(hh + (size_t)s3 * 128 + lane * 4);
        float2 a, b;
        a = __half22float2(*(__half2*)&u0.x); acc[0] += a.x; acc[1] += a.y;
        b = __half22float2(*(__half2*)&u0.y); acc[2] += b.x; acc[3] += b.y;
        a = __half22float2(*(__half2*)&u1.x); acc[0] += a.x; acc[1] += a.y;
        b = __half22float2(*(__half2*)&u1.y); acc[2] += b.x; acc[3] += b.y;
        a = __half22float2(*(__half2*)&u2.x); acc[0] += a.x; acc[1] += a.y;
        b = __half22float2(*(__half2*)&u2.y); acc[2] += b.x; acc[3] += b.y;
        a = __half22float2(*(__half2*)&u3.x); acc[0] += a.x; acc[1] += a.y;
        b = __half22float2(*(__half2*)&u3.y); acc[2] += b.x; acc[3] += b.y;
    }
    for (; i < e; i++) {
        uint2 u0 = *(const uint2*)(hh + (size_t)eidx[i] * 128 + lane * 4);
        float2 a = __half22float2(*(__half2*)&u0.x);
        float2 b = __half22float2(*(__half2*)&u0.y);
        acc[0] += a.x; acc[1] += a.y; acc[2] += b.x; acc[3] += b.y;
    }

    float iv = inv[warp];
    __half2 p0 = __float22half2_rn(make_float2(acc[0]*iv, acc[1]*iv));
    __half2 p1 = __float22half2_rn(make_float2(acc[2]*iv, acc[3]*iv));
    uint2 st;
    st.x = *(unsigned*)&p0; st.y = *(unsigned*)&p1;
    *(uint2*)(out + (size_t)warp * 128 + lane * 4) = st;
}

// Layer-3 fused aggregate: mean(th 64-wide) + ts[n,c] + bl3[c] -> out (fp32)
__global__ void aggregate_final_kernel(const int* __restrict__ rowptr,
                                       const int* __restrict__ eidx,
                                       const __half* __restrict__ th,   // N x 64
                                       const float* __restrict__ ts,    // N x 64
                                       const float* __restrict__ bl,
                                       const float* __restrict__ inv,
                                       float* __restrict__ out) {
    int warp = (blockIdx.x * blockDim.x + threadIdx.x) >> 5;
    int lane = threadIdx.x & 31;
    if (warp >= NNODES) return;
    int s = rowptr[warp];
    int e = rowptr[warp + 1];

    float a0 = 0.f, a1 = 0.f;
    int i = s;
    for (; i + 3 < e; i += 4) {
        int s0 = eidx[i], s1 = eidx[i+1], s2 = eidx[i+2], s3 = eidx[i+3];
        unsigned u0 = *(const unsigned*)(th + (size_t)s0 * 64 + lane * 2);
        unsigned u1 = *(const unsigned*)(th + (size_t)s1 * 64 + lane * 2);
        unsigned u2 = *(const unsigned*)(th + (size_t)s2 * 64 + lane * 2);
        unsigned u3 = *(const unsigned*)(th + (size_t)s3 * 64 + lane * 2);
        float2 a;
        a = __half22float2(*(__half2*)&u0); a0 += a.x; a1 += a.y;
        a = __half22float2(*(__half2*)&u1); a0 += a.x; a1 += a.y;
        a = __half22float2(*(__half2*)&u2); a0 += a.x; a1 += a.y;
        a = __half22float2(*(__half2*)&u3); a0 += a.x; a1 += a.y;
    }
    for (; i < e; i++) {
        unsigned u0 = *(const unsigned*)(th + (size_t)eidx[i] * 64 + lane * 2);
        float2 a = __half22float2(*(__half2*)&u0);
        a0 += a.x; a1 += a.y;
    }

    float iv = inv[warp];
    float2 self = *(const float2*)(ts + (size_t)warp * 64 + lane * 2);
    float2 bb   = *(const float2*)(bl + lane * 2);
    *(float2*)(out + (size_t)warp * 64 + lane * 2) =
        make_float2(a0 * iv + self.x + bb.x, a1 * iv + self.y + bb.y);
}

// ---------------------------------------------------------------------------
// Tensor-core GEMM pieces (mma.sync m16n8k16, fp16 in / fp32 accum)
#define MMA_16816(c, a, b) \
    asm volatile("mma.sync.aligned.m16n8k16.row.col.f32.f16.f16.f32 " \
        "{%0,%1,%2,%3}, {%4,%5,%6,%7}, {%8,%9}, {%0,%1,%2,%3};" \
        : "+f"((c)[0]), "+f"((c)[1]), "+f"((c)[2]), "+f"((c)[3]) \
        : "r"((a)[0]), "r"((a)[1]), "r"((a)[2]), "r"((a)[3]), \
          "r"((b)[0]), "r"((b)[1]))

__device__ __forceinline__ uint4 f8h8(float4 f0, float4 f1) {
    __half2 h0 = __float22half2_rn(make_float2(f0.x, f0.y));
    __half2 h1 = __float22half2_rn(make_float2(f0.z, f0.w));
    __half2 h2 = __float22half2_rn(make_float2(f1.x, f1.y));
    __half2 h3 = __float22half2_rn(make_float2(f1.z, f1.w));
    uint4 v;
    v.x = *(unsigned*)&h0; v.y = *(unsigned*)&h1;
    v.z = *(unsigned*)&h2; v.w = *(unsigned*)&h3;
    return v;
}

// combine: outh[n,c] = relu( mean@Wl^T + bl + h@Wr^T )  -> fp16, tight 128
__global__ __launch_bounds__(256)
void combine_tc(const __half* __restrict__ mean, const __half* __restrict__ h,
                const float* __restrict__ Wl, const float* __restrict__ bl,
                const float* __restrict__ Wr, __half* __restrict__ outh) {
    constexpr int BM = 128, BN = 128, BK = 64, LD = 72;
    __shared__ __half As[BM][LD];
    __shared__ __half Bs[BN][LD];

    const int tid = threadIdx.x, wid = tid >> 5, lane = tid & 31;
    const int m0 = blockIdx.x * BM;
    const int wm = (wid & 3) * 32;
    const int wn = (wid >> 2) * 64;

    float acc[2][8][4];
#pragma unroll
    for (int i = 0; i < 2; i++)
#pragma unroll
        for (int j = 0; j < 8; j++)
#pragma unroll
            for (int d = 0; d < 4; d++) acc[i][j][d] = 0.f;

#pragma unroll
    for (int phase = 0; phase < 2; phase++) {
        const __half* A = phase ? h  : mean;
        const float*  B = phase ? Wr : Wl;
#pragma unroll
        for (int kc = 0; kc < CDIM; kc += BK) {
            __syncthreads();
#pragma unroll
            for (int s = tid; s < BM * BK / 8; s += 256) {
                int m = s >> 3, kg = (s & 7) * 8;
                uint4 v = make_uint4(0, 0, 0, 0);
                int node = m0 + m;
                if (node < NNODES)
                    v = *(const uint4*)(A + (size_t)node * CDIM + kc + kg);
                *(uint4*)&As[m][kg] = v;
            }
#pragma unroll
            for (int s = tid; s < BN * BK / 8; s += 256) {
                int c = s >> 3, kg = (s & 7) * 8;
                const float4* p = (const float4*)(B + (size_t)c * CDIM + kc + kg);
                *(uint4*)&Bs[c][kg] = f8h8(p[0], p[1]);
            }
            __syncthreads();

#pragma unroll
            for (int ks = 0; ks < 4; ks++) {
                int k0 = ks * 16;
                unsigned a[2][4];
#pragma unroll
                for (int mf = 0; mf < 2; mf++) {
                    int row = wm + mf * 16 + (lane & 15);
                    int col = k0 + ((lane >> 4) << 3);
                    unsigned addr = (unsigned)__cvta_generic_to_shared(&As[row][col]);
                    asm volatile("ldmatrix.sync.aligned.m8n8.x4.shared.b16 {%0,%1,%2,%3}, [%4];"
                        : "=r"(a[mf][0]), "=r"(a[mf][1]), "=r"(a[mf][2]), "=r"(a[mf][3])
                        : "r"(addr));
                }
#pragma unroll
                for (int nf = 0; nf < 8; nf++) {
                    int l = lane & 15;
                    int rown = wn + nf * 8 + (l & 7);
                    int col = k0 + ((l >> 3) << 3);
                    unsigned addr = (unsigned)__cvta_generic_to_shared(&Bs[rown][col]);
                    unsigned b[2];
                    asm volatile("ldmatrix.sync.aligned.m8n8.x2.shared.b16 {%0,%1}, [%2];"
                        : "=r"(b[0]), "=r"(b[1]) : "r"(addr));
                    MMA_16816(acc[0][nf], a[0], b);
                    MMA_16816(acc[1][nf], a[1], b);
                }
            }
        }
    }

    const int tg = lane >> 2;
    const int tc = (lane & 3) * 2;
#pragma unroll
    for (int mf = 0; mf < 2; mf++) {
#pragma unroll
        for (int nf = 0; nf < 8; nf++) {
            int n_ = wn + nf * 8 + tc;
            float b0 = bl[n_], b1 = bl[n_ + 1];
            int mA = m0 + wm + mf * 16 + tg;
            int mB = mA + 8;
            if (mA < NNODES) {
                __half2 hv = __float22half2_rn(make_float2(
                    fmaxf(acc[mf][nf][0] + b0, 0.f), fmaxf(acc[mf][nf][1] + b1, 0.f)));
                *(__half2*)(outh + (size_t)mA * BN + n_) = hv;
            }
            if (mB < NNODES) {
                __half2 hv = __float22half2_rn(make_float2(
                    fmaxf(acc[mf][nf][2] + b0, 0.f), fmaxf(acc[mf][nf][3] + b1, 0.f)));
                *(__half2*)(outh + (size_t)mB * BN + n_) = hv;
            }
        }
    }
}

// proj: cols 0..63 = h@Wl3^T -> th (fp16); cols 64..127 = h@Wr3^T -> ts (fp32)
__global__ __launch_bounds__(256)
void proj_tc(const __half* __restrict__ h,
             const float* __restrict__ Wl, const float* __restrict__ Wr,
             __half* __restrict__ th, float* __restrict__ ts) {
    constexpr int BM = 128, BN = 128, BK = 64, LD = 72;
    __shared__ __half As[BM][LD];
    __shared__ __half Bs[BN][LD];

    const int tid = threadIdx.x, wid = tid >> 5, lane = tid & 31;
    const int m0 = blockIdx.x * BM;
    const int wm = (wid & 3) * 32;
    const int wn = (wid >> 2) * 64;

    float acc[2][8][4];
#pragma unroll
    for (int i = 0; i < 2; i++)
#pragma unroll
        for (int j = 0; j < 8; j++)
#pragma unroll
            for (int d = 0; d < 4; d++) acc[i][j][d] = 0.f;

#pragma unroll
    for (int kc = 0; kc < CDIM; kc += BK) {
        __syncthreads();
#pragma unroll
        for (int s = tid; s < BM * BK / 8; s += 256) {
            int m = s >> 3, kg = (s & 7) * 8;
            uint4 v = make_uint4(0, 0, 0, 0);
            int node = m0 + m;
            if (node < NNODES)
                v = *(const uint4*)(h + (size_t)node * CDIM + kc + kg);
            *(uint4*)&As[m][kg] = v;
        }
#pragma unroll
        for (int s = tid; s < BN * BK / 8; s += 256) {
            int c = s >> 3, kg = (s & 7) * 8;
            const float* w = (c < 64) ? (Wl + (size_t)c * CDIM)
                                      : (Wr + (size_t)(c - 64) * CDIM);
            const float4* p = (const float4*)(w + kc + kg);
            *(uint4*)&Bs[c][kg] = f8h8(p[0], p[1]);
        }
        __syncthreads();

#pragma unroll
        for (int ks = 0; ks < 4; ks++) {
            int k0 = ks * 16;
            unsigned a[2][4];
#pragma unroll
            for (int mf = 0; mf < 2; mf++) {
                int row = wm + mf * 16 + (lane & 15);
                int col = k0 + ((lane >> 4) << 3);
                unsigned addr = (unsigned)__cvta_generic_to_shared(&As[row][col]);
                asm volatile("ldmatrix.sync.aligned.m8n8.x4.shared.b16 {%0,%1,%2,%3}, [%4];"
                    : "=r"(a[mf][0]), "=r"(a[mf][1]), "=r"(a[mf][2]), "=r"(a[mf][3])
                    : "r"(addr));
            }
#pragma unroll
            for (int nf = 0; nf < 8; nf++) {
                int l = lane & 15;
                int rown = wn + nf * 8 + (l & 7);
                int col = k0 + ((l >> 3) << 3);
                unsigned addr = (unsigned)__cvta_generic_to_shared(&Bs[rown][col]);
                unsigned b[2];
                asm volatile("ldmatrix.sync.aligned.m8n8.x2.shared.b16 {%0,%1}, [%2];"
                    : "=r"(b[0]), "=r"(b[1]) : "r"(addr));
                MMA_16816(acc[0][nf], a[0], b);
                MMA_16816(acc[1][nf], a[1], b);
            }
        }
    }

    const int tg = lane >> 2;
    const int tc = (lane & 3) * 2;
#pragma unroll
    for (int mf = 0; mf < 2; mf++) {
#pragma unroll
        for (int nf = 0; nf < 8; nf++) {
            int n_ = wn + nf * 8 + tc;
            int mA = m0 + wm + mf * 16 + tg;
            int mB = mA + 8;
            if (n_ < 64) {
                if (mA < NNODES)
                    *(__half2*)(th + (size_t)mA * 64 + n_) = __float22half2_rn(
                        make_float2(acc[mf][nf][0], acc[mf][nf][1]));
                if (mB < NNODES)
                    *(__half2*)(th + (size_t)mB * 64 + n_) = __float22half2_rn(
                        make_float2(acc[mf][nf][2], acc[mf][nf][3]));
            } else {
                int c = n_ - 64;
                if (mA < NNODES)
                    *(float2*)(ts + (size_t)mA * 64 + c) =
                        make_float2(acc[mf][nf][0], acc[mf][nf][1]);
                if (mB < NNODES)
                    *(float2*)(ts + (size_t)mB * 64 + c) =
                        make_float2(acc[mf][nf][2], acc[mf][nf][3]);
            }
        }
    }
}

// ---------------------------------------------------------------------------
extern "C" void kernel_launch(void* const* d_in, const int* in_sizes, int n_in,
                              void* d_out, int out_size) {
    const float* x   = (const float*)d_in[0];
    const int*   ei  = (const int*)d_in[1];      // int32 (JAX x64 disabled)
    const float* Wl1 = (const float*)d_in[2];
    const float* bl1 = (const float*)d_in[3];
    const float* Wr1 = (const float*)d_in[4];
    const float* Wl2 = (const float*)d_in[5];
    const float* bl2 = (const float*)d_in[6];
    const float* Wr2 = (const float*)d_in[7];
    const float* Wl3 = (const float*)d_in[8];
    const float* bl3 = (const float*)d_in[9];
    const float* Wr3 = (const float*)d_in[10];
    float* out = (float*)d_out;

    __half *xh, *aggh, *h1h, *h2h, *th;
    float *ts, *inv;
    int *deg, *rowptr, *wcur, *eidx, *bsum;
    cudaGetSymbolAddress((void**)&xh,   g_xh);
    cudaGetSymbolAddress((void**)&aggh, g_aggh);
    cudaGetSymbolAddress((void**)&h1h,  g_h1h);
    cudaGetSymbolAddress((void**)&h2h,  g_h2h);
    cudaGetSymbolAddress((void**)&th,   g_th);
    cudaGetSymbolAddress((void**)&ts,   g_ts);
    cudaGetSymbolAddress((void**)&inv,  g_inv);
    cudaGetSymbolAddress((void**)&deg,  g_deg);
    cudaGetSymbolAddress((void**)&rowptr, g_rowptr);
    cudaGetSymbolAddress((void**)&wcur, g_wcur);
    cudaGetSymbolAddress((void**)&eidx, g_eidx);
    cudaGetSymbolAddress((void**)&bsum, g_bsum);

    const int e4Blocks = (EDGES / 4 + 255) / 256;
    const int aggBlocks = (NNODES * 32 + 255) / 256;   // warp per node
    const int combBlocks = (NNODES + 127) / 128;
    const int cvtBlocks = (int)(((long long)NNODES * CDIM / 8 + 255) / 256);

    // --- CSR build (once per launch) ---
    cudaMemsetAsync(deg, 0, NNODES * sizeof(int), 0);
    hist_kernel<<<e4Blocks, 256>>>(ei, deg);
    partial_kernel<<<NB_SCAN, 256>>>(deg, bsum);
    scanb_kernel<<<1, 512>>>(bsum);
    rescan_kernel<<<NB_SCAN, 256>>>(deg, bsum, rowptr, wcur, inv);
    fill_kernel<<<e4Blocks, 256>>>(ei, wcur, eidx);

    // --- Layer 1: x -> h1h (relu) ---
    tohalf_kernel<<<cvtBlocks, 256>>>(x, xh);
    aggregate128_kernel<<<aggBlocks, 256>>>(rowptr, eidx, xh, inv, aggh);
    combine_tc<<<combBlocks, 256>>>(aggh, xh, Wl1, bl1, Wr1, h1h);

    // --- Layer 2: h1h -> h2h (relu) ---
    aggregate128_kernel<<<aggBlocks, 256>>>(rowptr, eidx, h1h, inv, aggh);
    combine_tc<<<combBlocks, 256>>>(aggh, h1h, Wl2, bl2, Wr2, h2h);

    // --- Layer 3: proj (th fp16 / ts fp32), fused 64-wide aggregate ---
    proj_tc<<<combBlocks, 256>>>(h2h, Wl3, Wr3, th, ts);
    aggregate_final_kernel<<<aggBlocks, 256>>>(rowptr, eidx, th, ts, bl3, inv, out);
}

// round 14
// speedup vs baseline: 1.9434x; 1.0067x over previous
#include <cuda_runtime.h>
#include <cuda_fp16.h>

#define NNODES 100000
#define CDIM   128
#define EDGES  3200000
#define NB_SCAN 391   // ceil(NNODES/256)

// prep kernel block partition
#define XBLK 6250     // NNODES*CDIM/8/256
#define WBLK 40       // 81920 weight halves /8/256
#define HBLK 1563     // ceil(EDGES/8/256)

// Scratch (__device__ globals; no allocation allowed). fp16 feature plane.
__device__ __half g_xh  [(size_t)NNODES * CDIM];
__device__ __half g_aggh[(size_t)NNODES * CDIM];
__device__ __half g_h1h [(size_t)NNODES * CDIM];
__device__ __half g_h2h [(size_t)NNODES * CDIM];
__device__ __half g_th  [(size_t)NNODES * 64];    // proj cols 0..63 (fp16)
__device__ float  g_ts  [(size_t)NNODES * 64];    // proj cols 64..127 (fp32 self)
__device__ __half g_wh  [81920];                  // fp16 weights, concatenated
__device__ float  g_inv[NNODES];
__device__ int    g_deg[NNODES];
__device__ int    g_rowptr[NNODES + 1];
__device__ int    g_wcur[NNODES];
__device__ int    g_eidx[EDGES];
__device__ int    g_bsum[NB_SCAN];

// ---------------------------------------------------------------------------
__device__ __forceinline__ uint4 f8h8_(float4 f0, float4 f1) {
    __half2 h0 = __float22half2_rn(make_float2(f0.x, f0.y));
    __half2 h1 = __float22half2_rn(make_float2(f0.z, f0.w));
    __half2 h2 = __float22half2_rn(make_float2(f1.x, f1.y));
    __half2 h3 = __float22half2_rn(make_float2(f1.z, f1.w));
    uint4 v;
    v.x = *(unsigned*)&h0; v.y = *(unsigned*)&h1;
    v.z = *(unsigned*)&h2; v.w = *(unsigned*)&h3;
    return v;
}

// ---------------------------------------------------------------------------
// PREP (grid-partitioned, independent work): x->fp16, weights->fp16, degree hist
__global__ void prep_kernel(const float* __restrict__ x, __half* __restrict__ xh,
                            const float* __restrict__ Wl1, const float* __restrict__ Wr1,
                            const float* __restrict__ Wl2, const float* __restrict__ Wr2,
                            const float* __restrict__ Wl3, const float* __restrict__ Wr3,
                            __half* __restrict__ wh,
                            const int* __restrict__ ei, int* __restrict__ deg) {
    int b = blockIdx.x;
    if (b < XBLK) {
        long long i = (long long)b * 256 + threadIdx.x;        // 8 floats each
        const float4* p = (const float4*)(x + i * 8);
        *(uint4*)(xh + i * 8) = f8h8_(p[0], p[1]);
    } else if (b < XBLK + WBLK) {
        int wi = (b - XBLK) * 256 + threadIdx.x;               // 8 elems each
        int off = wi * 8;
        const float* src;
        if      (off < 16384) src = Wl1 + off;
        else if (off < 32768) src = Wr1 + off - 16384;
        else if (off < 49152) src = Wl2 + off - 32768;
        else if (off < 65536) src = Wr2 + off - 49152;
        else if (off < 73728) src = Wl3 + off - 65536;
        else                  src = Wr3 + off - 73728;
        const float4* p = (const float4*)src;
        *(uint4*)(wh + off) = f8h8_(p[0], p[1]);
    } else {
        int e8 = ((b - XBLK - WBLK) * 256 + threadIdx.x) * 8;
        if (e8 + 7 < EDGES) {
            int4 d0 = *(const int4*)(ei + EDGES + e8);
            int4 d1 = *(const int4*)(ei + EDGES + e8 + 4);
            atomicAdd(deg + d0.x, 1); atomicAdd(deg + d0.y, 1);
            atomicAdd(deg + d0.z, 1); atomicAdd(deg + d0.w, 1);
            atomicAdd(deg + d1.x, 1); atomicAdd(deg + d1.y, 1);
            atomicAdd(deg + d1.z, 1); atomicAdd(deg + d1.w, 1);
        } else {
            for (int e = e8; e < EDGES; e++)
                atomicAdd(deg + ei[EDGES + e], 1);
        }
    }
}

// ---------------------------------------------------------------------------
// scan step a: per-256-chunk partial sums
__global__ void partial_kernel(const int* __restrict__ deg, int* __restrict__ bsum) {
    int i = blockIdx.x * 256 + threadIdx.x;
    int v = (i < NNODES) ? deg[i] : 0;
#pragma unroll
    for (int off = 16; off > 0; off >>= 1)
        v += __shfl_down_sync(0xffffffffu, v, off);
    __shared__ int ws[8];
    int wid = threadIdx.x >> 5, lane = threadIdx.x & 31;
    if (lane == 0) ws[wid] = v;
    __syncthreads();
    if (wid == 0 && lane < 8) {
        int s = ws[lane];
#pragma unroll
        for (int off = 4; off > 0; off >>= 1)
            s += __shfl_down_sync(0x000000ffu, s, off);
        if (lane == 0) bsum[blockIdx.x] = s;
    }
}

// scan step b: exclusive scan of block sums
__global__ void scanb_kernel(int* __restrict__ bsum) {
    int t = threadIdx.x;
    int v = (t < NB_SCAN) ? bsum[t] : 0;
    int x = v;
#pragma unroll
    for (int off = 1; off < 32; off <<= 1) {
        int y = __shfl_up_sync(0xffffffffu, x, off);
        if ((t & 31) >= off) x += y;
    }
    __shared__ int ws[16];
    int wid = t >> 5, lane = t & 31;
    if (lane == 31) ws[wid] = x;
    __syncthreads();
    if (wid == 0 && lane < 16) {
        int s = ws[lane];
#pragma unroll
        for (int off = 1; off < 16; off <<= 1) {
            int y = __shfl_up_sync(0x0000ffffu, s, off);
            if (lane >= off) s += y;
        }
        ws[lane] = s;
    }
    __syncthreads();
    int woff = (wid > 0) ? ws[wid - 1] : 0;
    if (t < NB_SCAN) bsum[t] = woff + x - v;   // exclusive
}

// scan step c: re-scan -> rowptr + wcur + inv + rowptr[NNODES]
__global__ void rescan_kernel(const int* __restrict__ deg, const int* __restrict__ bsum,
                              int* __restrict__ rowptr, int* __restrict__ wcur,
                              float* __restrict__ inv) {
    int i = blockIdx.x * 256 + threadIdx.x;
    int v = (i < NNODES) ? deg[i] : 0;
    int x = v;
#pragma unroll
    for (int off = 1; off < 32; off <<= 1) {
        int y = __shfl_up_sync(0xffffffffu, x, off);
        if ((threadIdx.x & 31) >= off) x += y;
    }
    __shared__ int ws[8];
    int wid = threadIdx.x >> 5, lane = threadIdx.x & 31;
    if (lane == 31) ws[wid] = x;
    __syncthreads();
    if (wid == 0 && lane < 8) {
        int s = ws[lane];
#pragma unroll
        for (int off = 1; off < 8; off <<= 1) {
            int y = __shfl_up_sync(0x000000ffu, s, off);
            if (lane >= off) s += y;
        }
        ws[lane] = s;
    }
    __syncthreads();
    int woff = (wid > 0) ? ws[wid - 1] : 0;
    if (i < NNODES) {
        int rp = bsum[blockIdx.x] + woff + x - v;
        rowptr[i] = rp;
        wcur[i]   = rp;
        inv[i]    = 1.0f / fmaxf((float)v, 1.0f);
        if (i == 0) rowptr[NNODES] = EDGES;
    }
}

// fill CSR adjacency, 8 edges per thread (ILP)
__global__ void fill_kernel(const int* __restrict__ ei, int* __restrict__ wcur,
                            int* __restrict__ eidx) {
    int e8 = (blockIdx.x * blockDim.x + threadIdx.x) * 8;
    if (e8 + 7 < EDGES) {
        int4 s0 = *(const int4*)(ei + e8);
        int4 s1 = *(const int4*)(ei + e8 + 4);
        int4 d0 = *(const int4*)(ei + EDGES + e8);
        int4 d1 = *(const int4*)(ei + EDGES + e8 + 4);
        int p0 = atomicAdd(wcur + d0.x, 1);
        int p1 = atomicAdd(wcur + d0.y, 1);
        int p2 = atomicAdd(wcur + d0.z, 1);
        int p3 = atomicAdd(wcur + d0.w, 1);
        int p4 = atomicAdd(wcur + d1.x, 1);
        int p5 = atomicAdd(wcur + d1.y, 1);
        int p6 = atomicAdd(wcur + d1.z, 1);
        int p7 = atomicAdd(wcur + d1.w, 1);
        eidx[p0] = s0.x; eidx[p1] = s0.y; eidx[p2] = s0.z; eidx[p3] = s0.w;
        eidx[p4] = s1.x; eidx[p5] = s1.y; eidx[p6] = s1.z; eidx[p7] = s1.w;
    } else {
        for (int e = e8; e < EDGES; e++) {
            int pos = atomicAdd(wcur + ei[EDGES + e], 1);
            eidx[pos] = ei[e];
        }
    }
}

// ---------------------------------------------------------------------------
// Gather-aggregate (fp16 in, fp32 accumulate, fp16 mean out): warp per node.
__global__ void aggregate128_kernel(const int* __restrict__ rowptr,
                                    const int* __restrict__ eidx,
                                    const __half* __restrict__ hh,
                                    const float* __restrict__ inv,
                                    __half* __restrict__ out) {
    int warp = (blockIdx.x * blockDim.x + threadIdx.x) >> 5;
    int lane = threadIdx.x & 31;
    if (warp >= NNODES) return;
    int s = rowptr[warp];
    int e = rowptr[warp + 1];

    float acc[4] = {0.f, 0.f, 0.f, 0.f};

    int i = s;
    for (; i + 3 < e; i += 4) {
        int s0 = eidx[i], s1 = eidx[i+1], s2 = eidx[i+2], s3 = eidx[i+3];
        uint2 u0 = *(const uint2*)(hh + (size_t)s0 * 128 + lane * 4);
        uint2 u1 = *(const uint2*)(hh + (size_t)s1 * 128 + lane * 4);
        uint2 u2 = *(const uint2*)(hh + (size_t)s2 * 128 + lane * 4);
        uint2 u3 = *(const uint2*)(hh + (size_t)s3 * 128 + lane * 4);
        float2 a, b;
        a = __half22float2(*(__half2*)&u0.x); acc[0] += a.x; acc[1] += a.y;
        b = __half22float2(*(__half2*)&u0.y); acc[2] += b.x; acc[3] += b.y;
        a = __half22float2(*(__half2*)&u1.x); acc[0] += a.x; acc[1] += a.y;
        b = __half22float2(*(__half2*)&u1.y); acc[2] += b.x; acc[3] += b.y;
        a = __half22float2(*(__half2*)&u2.x); acc[0] += a.x; acc[1] += a.y;
        b = __half22float2(*(__half2*)&u2.y); acc[2] += b.x; acc[3] += b.y;
        a = __half22float2(*(__half2*)&u3.x); acc[0] += a.x; acc[1] += a.y;
        b = __half22float2(*(__half2*)&u3.y); acc[2] += b.x; acc[3] += b.y;
    }
    for (; i < e; i++) {
        uint2 u0 = *(const uint2*)(hh + (size_t)eidx[i] * 128 + lane * 4);
        float2 a = __half22float2(*(__half2*)&u0.x);
        float2 b = __half22float2(*(__half2*)&u0.y);
        acc[0] += a.x; acc[1] += a.y; acc[2] += b.x; acc[3] += b.y;
    }

    float iv = inv[warp];
    __half2 p0 = __float22half2_rn(make_float2(acc[0]*iv, acc[1]*iv));
    __half2 p1 = __float22half2_rn(make_float2(acc[2]*iv, acc[3]*iv));
    uint2 st;
    st.x = *(unsigned*)&p0; st.y = *(unsigned*)&p1;
    *(uint2*)(out + (size_t)warp * 128 + lane * 4) = st;
}

// Layer-3 fused aggregate: mean(th 64-wide) + ts[n,c] + bl3[c] -> out (fp32)
__global__ void aggregate_final_kernel(const int* __restrict__ rowptr,
                                       const int* __restrict__ eidx,
                                       const __half* __restrict__ th,
                                       const float* __restrict__ ts,
                                       const float* __restrict__ bl,
                                       const float* __restrict__ inv,
                                       float* __restrict__ out) {
    int warp = (blockIdx.x * blockDim.x + threadIdx.x) >> 5;
    int lane = threadIdx.x & 31;
    if (warp >= NNODES) return;
    int s = rowptr[warp];
    int e = rowptr[warp + 1];

    float a0 = 0.f, a1 = 0.f;
    int i = s;
    for (; i + 3 < e; i += 4) {
        int s0 = eidx[i], s1 = eidx[i+1], s2 = eidx[i+2], s3 = eidx[i+3];
        unsigned u0 = *(const unsigned*)(th + (size_t)s0 * 64 + lane * 2);
        unsigned u1 = *(const unsigned*)(th + (size_t)s1 * 64 + lane * 2);
        unsigned u2 = *(const unsigned*)(th + (size_t)s2 * 64 + lane * 2);
        unsigned u3 = *(const unsigned*)(th + (size_t)s3 * 64 + lane * 2);
        float2 a;
        a = __half22float2(*(__half2*)&u0); a0 += a.x; a1 += a.y;
        a = __half22float2(*(__half2*)&u1); a0 += a.x; a1 += a.y;
        a = __half22float2(*(__half2*)&u2); a0 += a.x; a1 += a.y;
        a = __half22float2(*(__half2*)&u3); a0 += a.x; a1 += a.y;
    }
    for (; i < e; i++) {
        unsigned u0 = *(const unsigned*)(th + (size_t)eidx[i] * 64 + lane * 2);
        float2 a = __half22float2(*(__half2*)&u0);
        a0 += a.x; a1 += a.y;
    }

    float iv = inv[warp];
    float2 self = *(const float2*)(ts + (size_t)warp * 64 + lane * 2);
    float2 bb   = *(const float2*)(bl + lane * 2);
    *(float2*)(out + (size_t)warp * 64 + lane * 2) =
        make_float2(a0 * iv + self.x + bb.x, a1 * iv + self.y + bb.y);
}

// ---------------------------------------------------------------------------
// Tensor-core GEMM pieces (mma.sync m16n8k16, fp16 in / fp32 accum)
#define MMA_16816(c, a, b) \
    asm volatile("mma.sync.aligned.m16n8k16.row.col.f32.f16.f16.f32 " \
        "{%0,%1,%2,%3}, {%4,%5,%6,%7}, {%8,%9}, {%0,%1,%2,%3};" \
        : "+f"((c)[0]), "+f"((c)[1]), "+f"((c)[2]), "+f"((c)[3]) \
        : "r"((a)[0]), "r"((a)[1]), "r"((a)[2]), "r"((a)[3]), \
          "r"((b)[0]), "r"((b)[1]))

// combine: outh[n,c] = relu( mean@Wl^T + bl + h@Wr^T )  -> fp16, tight 128
// All operands fp16 (weights pre-converted).
__global__ __launch_bounds__(256)
void combine_tc(const __half* __restrict__ mean, const __half* __restrict__ h,
                const __half* __restrict__ Wl, const float* __restrict__ bl,
                const __half* __restrict__ Wr, __half* __restrict__ outh) {
    constexpr int BM = 128, BN = 128, BK = 64, LD = 72;
    __shared__ __half As[BM][LD];
    __shared__ __half Bs[BN][LD];

    const int tid = threadIdx.x, wid = tid >> 5, lane = tid & 31;
    const int m0 = blockIdx.x * BM;
    const int wm = (wid & 3) * 32;
    const int wn = (wid >> 2) * 64;

    float acc[2][8][4];
#pragma unroll
    for (int i = 0; i < 2; i++)
#pragma unroll
        for (int j = 0; j < 8; j++)
#pragma unroll
            for (int d = 0; d < 4; d++) acc[i][j][d] = 0.f;

#pragma unroll
    for (int phase = 0; phase < 2; phase++) {
        const __half* A = phase ? h  : mean;
        const __half* B = phase ? Wr : Wl;
#pragma unroll
        for (int kc = 0; kc < CDIM; kc += BK) {
            __syncthreads();
#pragma unroll
            for (int s = tid; s < BM * BK / 8; s += 256) {
                int m = s >> 3, kg = (s & 7) * 8;
                uint4 v = make_uint4(0, 0, 0, 0);
                int node = m0 + m;
                if (node < NNODES)
                    v = *(const uint4*)(A + (size_t)node * CDIM + kc + kg);
                *(uint4*)&As[m][kg] = v;
            }
#pragma unroll
            for (int s = tid; s < BN * BK / 8; s += 256) {
                int c = s >> 3, kg = (s & 7) * 8;
                *(uint4*)&Bs[c][kg] = *(const uint4*)(B + (size_t)c * CDIM + kc + kg);
            }
            __syncthreads();

#pragma unroll
            for (int ks = 0; ks < 4; ks++) {
                int k0 = ks * 16;
                unsigned a[2][4];
#pragma unroll
                for (int mf = 0; mf < 2; mf++) {
                    int row = wm + mf * 16 + (lane & 15);
                    int col = k0 + ((lane >> 4) << 3);
                    unsigned addr = (unsigned)__cvta_generic_to_shared(&As[row][col]);
                    asm volatile("ldmatrix.sync.aligned.m8n8.x4.shared.b16 {%0,%1,%2,%3}, [%4];"
                        : "=r"(a[mf][0]), "=r"(a[mf][1]), "=r"(a[mf][2]), "=r"(a[mf][3])
                        : "r"(addr));
                }
#pragma unroll
                for (int nf = 0; nf < 8; nf++) {
                    int l = lane & 15;
                    int rown = wn + nf * 8 + (l & 7);
                    int col = k0 + ((l >> 3) << 3);
                    unsigned addr = (unsigned)__cvta_generic_to_shared(&Bs[rown][col]);
                    unsigned b[2];
                    asm volatile("ldmatrix.sync.aligned.m8n8.x2.shared.b16 {%0,%1}, [%2];"
                        : "=r"(b[0]), "=r"(b[1]) : "r"(addr));
                    MMA_16816(acc[0][nf], a[0], b);
                    MMA_16816(acc[1][nf], a[1], b);
                }
            }
        }
    }

    const int tg = lane >> 2;
    const int tc = (lane & 3) * 2;
#pragma unroll
    for (int mf = 0; mf < 2; mf++) {
#pragma unroll
        for (int nf = 0; nf < 8; nf++) {
            int n_ = wn + nf * 8 + tc;
            float b0 = bl[n_], b1 = bl[n_ + 1];
            int mA = m0 + wm + mf * 16 + tg;
            int mB = mA + 8;
            if (mA < NNODES) {
                __half2 hv = __float22half2_rn(make_float2(
                    fmaxf(acc[mf][nf][0] + b0, 0.f), fmaxf(acc[mf][nf][1] + b1, 0.f)));
                *(__half2*)(outh + (size_t)mA * BN + n_) = hv;
            }
            if (mB < NNODES) {
                __half2 hv = __float22half2_rn(make_float2(
                    fmaxf(acc[mf][nf][2] + b0, 0.f), fmaxf(acc[mf][nf][3] + b1, 0.f)));
                *(__half2*)(outh + (size_t)mB * BN + n_) = hv;
            }
        }
    }
}

// proj: cols 0..63 = h@Wl3^T -> th (fp16); cols 64..127 = h@Wr3^T -> ts (fp32)
__global__ __launch_bounds__(256)
void proj_tc(const __half* __restrict__ h,
             const __half* __restrict__ Wl, const __half* __restrict__ Wr,
             __half* __restrict__ th, float* __restrict__ ts) {
    constexpr int BM = 128, BN = 128, BK = 64, LD = 72;
    __shared__ __half As[BM][LD];
    __shared__ __half Bs[BN][LD];

    const int tid = threadIdx.x, wid = tid >> 5, lane = tid & 31;
    const int m0 = blockIdx.x * BM;
    const int wm = (wid & 3) * 32;
    const int wn = (wid >> 2) * 64;

    float acc[2][8][4];
#pragma unroll
    for (int i = 0; i < 2; i++)
#pragma unroll
        for (int j = 0; j < 8; j++)
#pragma unroll
            for (int d = 0; d < 4; d++) acc[i][j][d] = 0.f;

#pragma unroll
    for (int kc = 0; kc < CDIM; kc += BK) {
        __syncthreads();
#pragma unroll
        for (int s = tid; s < BM * BK / 8; s += 256) {
            int m = s >> 3, kg = (s & 7) * 8;
            uint4 v = make_uint4(0, 0, 0, 0);
            int node = m0 + m;
            if (node < NNODES)
                v = *(const uint4*)(h + (size_t)node * CDIM + kc + kg);
            *(uint4*)&As[m][kg] = v;
        }
#pragma unroll
        for (int s = tid; s < BN * BK / 8; s += 256) {
            int c = s >> 3, kg = (s & 7) * 8;
            const __half* w = (c < 64) ? (Wl + (size_t)c * CDIM)
                                       : (Wr + (size_t)(c - 64) * CDIM);
            *(uint4*)&Bs[c][kg] = *(const uint4*)(w + kc + kg);
        }
        __syncthreads();

#pragma unroll
        for (int ks = 0; ks < 4; ks++) {
            int k0 = ks * 16;
            unsigned a[2][4];
#pragma unroll
            for (int mf = 0; mf < 2; mf++) {
                int row = wm + mf * 16 + (lane & 15);
                int col = k0 + ((lane >> 4) << 3);
                unsigned addr = (unsigned)__cvta_generic_to_shared(&As[row][col]);
                asm volatile("ldmatrix.sync.aligned.m8n8.x4.shared.b16 {%0,%1,%2,%3}, [%4];"
                    : "=r"(a[mf][0]), "=r"(a[mf][1]), "=r"(a[mf][2]), "=r"(a[mf][3])
                    : "r"(addr));
            }
#pragma unroll
            for (int nf = 0; nf < 8; nf++) {
                int l = lane & 15;
                int rown = wn + nf * 8 + (l & 7);
                int col = k0 + ((l >> 3) << 3);
                unsigned addr = (unsigned)__cvta_generic_to_shared(&Bs[rown][col]);
                unsigned b[2];
                asm volatile("ldmatrix.sync.aligned.m8n8.x2.shared.b16 {%0,%1}, [%2];"
                    : "=r"(b[0]), "=r"(b[1]) : "r"(addr));
                MMA_16816(acc[0][nf], a[0], b);
                MMA_16816(acc[1][nf], a[1], b);
            }
        }
    }

    const int tg = lane >> 2;
    const int tc = (lane & 3) * 2;
#pragma unroll
    for (int mf = 0; mf < 2; mf++) {
#pragma unroll
        for (int nf = 0; nf < 8; nf++) {
            int n_ = wn + nf * 8 + tc;
            int mA = m0 + wm + mf * 16 + tg;
            int mB = mA + 8;
            if (n_ < 64) {
                if (mA < NNODES)
                    *(__half2*)(th + (size_t)mA * 64 + n_) = __float22half2_rn(
                        make_float2(acc[mf][nf][0], acc[mf][nf][1]));
                if (mB < NNODES)
                    *(__half2*)(th + (size_t)mB * 64 + n_) = __float22half2_rn(
                        make_float2(acc[mf][nf][2], acc[mf][nf][3]));
            } else {
                int c = n_ - 64;
                if (mA < NNODES)
                    *(float2*)(ts + (size_t)mA * 64 + c) =
                        make_float2(acc[mf][nf][0], acc[mf][nf][1]);
                if (mB < NNODES)
                    *(float2*)(ts + (size_t)mB * 64 + c) =
                        make_float2(acc[mf][nf][2], acc[mf][nf][3]);
            }
        }
    }
}

// ---------------------------------------------------------------------------
extern "C" void kernel_launch(void* const* d_in, const int* in_sizes, int n_in,
                              void* d_out, int out_size) {
    const float* x   = (const float*)d_in[0];
    const int*   ei  = (const int*)d_in[1];      // int32 (JAX x64 disabled)
    const float* Wl1 = (const float*)d_in[2];
    const float* bl1 = (const float*)d_in[3];
    const float* Wr1 = (const float*)d_in[4];
    const float* Wl2 = (const float*)d_in[5];
    const float* bl2 = (const float*)d_in[6];
    const float* Wr2 = (const float*)d_in[7];
    const float* Wl3 = (const float*)d_in[8];
    const float* bl3 = (const float*)d_in[9];
    const float* Wr3 = (const float*)d_in[10];
    float* out = (float*)d_out;

    __half *xh, *aggh, *h1h, *h2h, *th, *wh;
    float *ts, *inv;
    int *deg, *rowptr, *wcur, *eidx, *bsum;
    cudaGetSymbolAddress((void**)&xh,   g_xh);
    cudaGetSymbolAddress((void**)&aggh, g_aggh);
    cudaGetSymbolAddress((void**)&h1h,  g_h1h);
    cudaGetSymbolAddress((void**)&h2h,  g_h2h);
    cudaGetSymbolAddress((void**)&th,   g_th);
    cudaGetSymbolAddress((void**)&ts,   g_ts);
    cudaGetSymbolAddress((void**)&wh,   g_wh);
    cudaGetSymbolAddress((void**)&inv,  g_inv);
    cudaGetSymbolAddress((void**)&deg,  g_deg);
    cudaGetSymbolAddress((void**)&rowptr, g_rowptr);
    cudaGetSymbolAddress((void**)&wcur, g_wcur);
    cudaGetSymbolAddress((void**)&eidx, g_eidx);
    cudaGetSymbolAddress((void**)&bsum, g_bsum);

    const __half* Wl1h = wh;
    const __half* Wr1h = wh + 16384;
    const __half* Wl2h = wh + 32768;
    const __half* Wr2h = wh + 49152;
    const __half* Wl3h = wh + 65536;
    const __half* Wr3h = wh + 73728;

    const int e8Blocks = (EDGES / 8 + 255) / 256;
    const int aggBlocks = (NNODES * 32 + 255) / 256;   // warp per node
    const int combBlocks = (NNODES + 127) / 128;

    // --- prep (x->fp16 | weights->fp16 | degree hist) + CSR build ---
    cudaMemsetAsync(deg, 0, NNODES * sizeof(int), 0);
    prep_kernel<<<XBLK + WBLK + HBLK, 256>>>(x, xh, Wl1, Wr1, Wl2, Wr2, Wl3, Wr3,
                                             wh, ei, deg);
    partial_kernel<<<NB_SCAN, 256>>>(deg, bsum);
    scanb_kernel<<<1, 512>>>(bsum);
    rescan_kernel<<<NB_SCAN, 256>>>(deg, bsum, rowptr, wcur, inv);
    fill_kernel<<<e8Blocks, 256>>>(ei, wcur, eidx);

    // --- Layer 1: x -> h1h (relu) ---
    aggregate128_kernel<<<aggBlocks, 256>>>(rowptr, eidx, xh, inv, aggh);
    combine_tc<<<combBlocks, 256>>>(aggh, xh, Wl1h, bl1, Wr1h, h1h);

    // --- Layer 2: h1h -> h2h (relu) ---
    aggregate128_kernel<<<aggBlocks, 256>>>(rowptr, eidx, h1h, inv, aggh);
    combine_tc<<<combBlocks, 256>>>(aggh, h1h, Wl2h, bl2, Wr2h, h2h);

    // --- Layer 3: proj (th fp16 / ts fp32), fused 64-wide aggregate ---
    proj_tc<<<combBlocks, 256>>>(h2h, Wl3h, Wr3h, th, ts);
    aggregate_final_kernel<<<aggBlocks, 256>>>(rowptr, eidx, th, ts, bl3, inv, out);
}

// round 16
// speedup vs baseline: 2.0275x; 1.0433x over previous
#include <cuda_runtime.h>
#include <cuda_fp16.h>

#define NNODES 100000
#define CDIM   128
#define EDGES  3200000
#define NB_SCAN 391   // ceil(NNODES/256)

// prep kernel block partition
#define XBLK 6250     // NNODES*CDIM/8/256
#define WBLK 40       // 81920 weight halves /8/256
#define HBLK 1563     // ceil(EDGES/8/256)

// Scratch (__device__ globals; no allocation allowed). fp16 feature plane.
__device__ __half g_xh  [(size_t)NNODES * CDIM];
__device__ __half g_aggh[(size_t)NNODES * CDIM];
__device__ __half g_h1h [(size_t)NNODES * CDIM];
__device__ __half g_th  [(size_t)NNODES * 64];    // proj cols 0..63 (fp16)
__device__ float  g_ts  [(size_t)NNODES * 64];    // proj cols 64..127 (fp32 self)
__device__ __half g_wh  [81920];                  // fp16 weights, concatenated
__device__ float  g_inv[NNODES];
__device__ int    g_deg[NNODES];
__device__ int    g_rowptr[NNODES + 1];
__device__ int    g_wcur[NNODES];
__device__ int    g_eidx[EDGES];
__device__ int    g_bsum[NB_SCAN];

// ---------------------------------------------------------------------------
__device__ __forceinline__ uint4 f8h8_(float4 f0, float4 f1) {
    __half2 h0 = __float22half2_rn(make_float2(f0.x, f0.y));
    __half2 h1 = __float22half2_rn(make_float2(f0.z, f0.w));
    __half2 h2 = __float22half2_rn(make_float2(f1.x, f1.y));
    __half2 h3 = __float22half2_rn(make_float2(f1.z, f1.w));
    uint4 v;
    v.x = *(unsigned*)&h0; v.y = *(unsigned*)&h1;
    v.z = *(unsigned*)&h2; v.w = *(unsigned*)&h3;
    return v;
}

// ---------------------------------------------------------------------------
// PREP (grid-partitioned): x->fp16, weights->fp16, degree hist
__global__ void prep_kernel(const float* __restrict__ x, __half* __restrict__ xh,
                            const float* __restrict__ Wl1, const float* __restrict__ Wr1,
                            const float* __restrict__ Wl2, const float* __restrict__ Wr2,
                            const float* __restrict__ Wl3, const float* __restrict__ Wr3,
                            __half* __restrict__ wh,
                            const int* __restrict__ ei, int* __restrict__ deg) {
    int b = blockIdx.x;
    if (b < XBLK) {
        long long i = (long long)b * 256 + threadIdx.x;
        const float4* p = (const float4*)(x + i * 8);
        *(uint4*)(xh + i * 8) = f8h8_(p[0], p[1]);
    } else if (b < XBLK + WBLK) {
        int wi = (b - XBLK) * 256 + threadIdx.x;
        int off = wi * 8;
        const float* src;
        if      (off < 16384) src = Wl1 + off;
        else if (off < 32768) src = Wr1 + off - 16384;
        else if (off < 49152) src = Wl2 + off - 32768;
        else if (off < 65536) src = Wr2 + off - 49152;
        else if (off < 73728) src = Wl3 + off - 65536;
        else                  src = Wr3 + off - 73728;
        const float4* p = (const float4*)src;
        *(uint4*)(wh + off) = f8h8_(p[0], p[1]);
    } else {
        int e8 = ((b - XBLK - WBLK) * 256 + threadIdx.x) * 8;
        if (e8 + 7 < EDGES) {
            int4 d0 = *(const int4*)(ei + EDGES + e8);
            int4 d1 = *(const int4*)(ei + EDGES + e8 + 4);
            atomicAdd(deg + d0.x, 1); atomicAdd(deg + d0.y, 1);
            atomicAdd(deg + d0.z, 1); atomicAdd(deg + d0.w, 1);
            atomicAdd(deg + d1.x, 1); atomicAdd(deg + d1.y, 1);
            atomicAdd(deg + d1.z, 1); atomicAdd(deg + d1.w, 1);
        } else {
            for (int e = e8; e < EDGES; e++)
                atomicAdd(deg + ei[EDGES + e], 1);
        }
    }
}

// ---------------------------------------------------------------------------
__global__ void partial_kernel(const int* __restrict__ deg, int* __restrict__ bsum) {
    int i = blockIdx.x * 256 + threadIdx.x;
    int v = (i < NNODES) ? deg[i] : 0;
#pragma unroll
    for (int off = 16; off > 0; off >>= 1)
        v += __shfl_down_sync(0xffffffffu, v, off);
    __shared__ int ws[8];
    int wid = threadIdx.x >> 5, lane = threadIdx.x & 31;
    if (lane == 0) ws[wid] = v;
    __syncthreads();
    if (wid == 0 && lane < 8) {
        int s = ws[lane];
#pragma unroll
        for (int off = 4; off > 0; off >>= 1)
            s += __shfl_down_sync(0x000000ffu, s, off);
        if (lane == 0) bsum[blockIdx.x] = s;
    }
}

__global__ void scanb_kernel(int* __restrict__ bsum) {
    int t = threadIdx.x;
    int v = (t < NB_SCAN) ? bsum[t] : 0;
    int x = v;
#pragma unroll
    for (int off = 1; off < 32; off <<= 1) {
        int y = __shfl_up_sync(0xffffffffu, x, off);
        if ((t & 31) >= off) x += y;
    }
    __shared__ int ws[16];
    int wid = t >> 5, lane = t & 31;
    if (lane == 31) ws[wid] = x;
    __syncthreads();
    if (wid == 0 && lane < 16) {
        int s = ws[lane];
#pragma unroll
        for (int off = 1; off < 16; off <<= 1) {
            int y = __shfl_up_sync(0x0000ffffu, s, off);
            if (lane >= off) s += y;
        }
        ws[lane] = s;
    }
    __syncthreads();
    int woff = (wid > 0) ? ws[wid - 1] : 0;
    if (t < NB_SCAN) bsum[t] = woff + x - v;   // exclusive
}

__global__ void rescan_kernel(const int* __restrict__ deg, const int* __restrict__ bsum,
                              int* __restrict__ rowptr, int* __restrict__ wcur,
                              float* __restrict__ inv) {
    int i = blockIdx.x * 256 + threadIdx.x;
    int v = (i < NNODES) ? deg[i] : 0;
    int x = v;
#pragma unroll
    for (int off = 1; off < 32; off <<= 1) {
        int y = __shfl_up_sync(0xffffffffu, x, off);
        if ((threadIdx.x & 31) >= off) x += y;
    }
    __shared__ int ws[8];
    int wid = threadIdx.x >> 5, lane = threadIdx.x & 31;
    if (lane == 31) ws[wid] = x;
    __syncthreads();
    if (wid == 0 && lane < 8) {
        int s = ws[lane];
#pragma unroll
        for (int off = 1; off < 8; off <<= 1) {
            int y = __shfl_up_sync(0x000000ffu, s, off);
            if (lane >= off) s += y;
        }
        ws[lane] = s;
    }
    __syncthreads();
    int woff = (wid > 0) ? ws[wid - 1] : 0;
    if (i < NNODES) {
        int rp = bsum[blockIdx.x] + woff + x - v;
        rowptr[i] = rp;
        wcur[i]   = rp;
        inv[i]    = 1.0f / fmaxf((float)v, 1.0f);
        if (i == 0) rowptr[NNODES] = EDGES;
    }
}

__global__ void fill_kernel(const int* __restrict__ ei, int* __restrict__ wcur,
                            int* __restrict__ eidx) {
    int e8 = (blockIdx.x * blockDim.x + threadIdx.x) * 8;
    if (e8 + 7 < EDGES) {
        int4 s0 = *(const int4*)(ei + e8);
        int4 s1 = *(const int4*)(ei + e8 + 4);
        int4 d0 = *(const int4*)(ei + EDGES + e8);
        int4 d1 = *(const int4*)(ei + EDGES + e8 + 4);
        int p0 = atomicAdd(wcur + d0.x, 1);
        int p1 = atomicAdd(wcur + d0.y, 1);
        int p2 = atomicAdd(wcur + d0.z, 1);
        int p3 = atomicAdd(wcur + d0.w, 1);
        int p4 = atomicAdd(wcur + d1.x, 1);
        int p5 = atomicAdd(wcur + d1.y, 1);
        int p6 = atomicAdd(wcur + d1.z, 1);
        int p7 = atomicAdd(wcur + d1.w, 1);
        eidx[p0] = s0.x; eidx[p1] = s0.y; eidx[p2] = s0.z; eidx[p3] = s0.w;
        eidx[p4] = s1.x; eidx[p5] = s1.y; eidx[p6] = s1.z; eidx[p7] = s1.w;
    } else {
        for (int e = e8; e < EDGES; e++) {
            int pos = atomicAdd(wcur + ei[EDGES + e], 1);
            eidx[pos] = ei[e];
        }
    }
}

// ---------------------------------------------------------------------------
// Gather-aggregate (fp16 in, fp32 accumulate, fp16 mean out): warp per node.
__global__ void aggregate128_kernel(const int* __restrict__ rowptr,
                                    const int* __restrict__ eidx,
                                    const __half* __restrict__ hh,
                                    const float* __restrict__ inv,
                                    __half* __restrict__ out) {
    int warp = (blockIdx.x * blockDim.x + threadIdx.x) >> 5;
    int lane = threadIdx.x & 31;
    if (warp >= NNODES) return;
    int s = rowptr[warp];
    int e = rowptr[warp + 1];

    float acc[4] = {0.f, 0.f, 0.f, 0.f};

    int i = s;
    for (; i + 3 < e; i += 4) {
        int s0 = eidx[i], s1 = eidx[i+1], s2 = eidx[i+2], s3 = eidx[i+3];
        uint2 u0 = *(const uint2*)(hh + (size_t)s0 * 128 + lane * 4);
        uint2 u1 = *(const uint2*)(hh + (size_t)s1 * 128 + lane * 4);
        uint2 u2 = *(const uint2*)(hh + (size_t)s2 * 128 + lane * 4);
        uint2 u3 = *(const uint2*)(hh + (size_t)s3 * 128 + lane * 4);
        float2 a, b;
        a = __half22float2(*(__half2*)&u0.x); acc[0] += a.x; acc[1] += a.y;
        b = __half22float2(*(__half2*)&u0.y); acc[2] += b.x; acc[3] += b.y;
        a = __half22float2(*(__half2*)&u1.x); acc[0] += a.x; acc[1] += a.y;
        b = __half22float2(*(__half2*)&u1.y); acc[2] += b.x; acc[3] += b.y;
        a = __half22float2(*(__half2*)&u2.x); acc[0] += a.x; acc[1] += a.y;
        b = __half22float2(*(__half2*)&u2.y); acc[2] += b.x; acc[3] += b.y;
        a = __half22float2(*(__half2*)&u3.x); acc[0] += a.x; acc[1] += a.y;
        b = __half22float2(*(__half2*)&u3.y); acc[2] += b.x; acc[3] += b.y;
    }
    for (; i < e; i++) {
        uint2 u0 = *(const uint2*)(hh + (size_t)eidx[i] * 128 + lane * 4);
        float2 a = __half22float2(*(__half2*)&u0.x);
        float2 b = __half22float2(*(__half2*)&u0.y);
        acc[0] += a.x; acc[1] += a.y; acc[2] += b.x; acc[3] += b.y;
    }

    float iv = inv[warp];
    __half2 p0 = __float22half2_rn(make_float2(acc[0]*iv, acc[1]*iv));
    __half2 p1 = __float22half2_rn(make_float2(acc[2]*iv, acc[3]*iv));
    uint2 st;
    st.x = *(unsigned*)&p0; st.y = *(unsigned*)&p1;
    *(uint2*)(out + (size_t)warp * 128 + lane * 4) = st;
}

// Layer-3 fused aggregate: mean(th 64-wide) + ts[n,c] + bl3[c] -> out (fp32)
__global__ void aggregate_final_kernel(const int* __restrict__ rowptr,
                                       const int* __restrict__ eidx,
                                       const __half* __restrict__ th,
                                       const float* __restrict__ ts,
                                       const float* __restrict__ bl,
                                       const float* __restrict__ inv,
                                       float* __restrict__ out) {
    int warp = (blockIdx.x * blockDim.x + threadIdx.x) >> 5;
    int lane = threadIdx.x & 31;
    if (warp >= NNODES) return;
    int s = rowptr[warp];
    int e = rowptr[warp + 1];

    float a0 = 0.f, a1 = 0.f;
    int i = s;
    for (; i + 3 < e; i += 4) {
        int s0 = eidx[i], s1 = eidx[i+1], s2 = eidx[i+2], s3 = eidx[i+3];
        unsigned u0 = *(const unsigned*)(th + (size_t)s0 * 64 + lane * 2);
        unsigned u1 = *(const unsigned*)(th + (size_t)s1 * 64 + lane * 2);
        unsigned u2 = *(const unsigned*)(th + (size_t)s2 * 64 + lane * 2);
        unsigned u3 = *(const unsigned*)(th + (size_t)s3 * 64 + lane * 2);
        float2 a;
        a = __half22float2(*(__half2*)&u0); a0 += a.x; a1 += a.y;
        a = __half22float2(*(__half2*)&u1); a0 += a.x; a1 += a.y;
        a = __half22float2(*(__half2*)&u2); a0 += a.x; a1 += a.y;
        a = __half22float2(*(__half2*)&u3); a0 += a.x; a1 += a.y;
    }
    for (; i < e; i++) {
        unsigned u0 = *(const unsigned*)(th + (size_t)eidx[i] * 64 + lane * 2);
        float2 a = __half22float2(*(__half2*)&u0);
        a0 += a.x; a1 += a.y;
    }

    float iv = inv[warp];
    float2 self = *(const float2*)(ts + (size_t)warp * 64 + lane * 2);
    float2 bb   = *(const float2*)(bl + lane * 2);
    *(float2*)(out + (size_t)warp * 64 + lane * 2) =
        make_float2(a0 * iv + self.x + bb.x, a1 * iv + self.y + bb.y);
}

// ---------------------------------------------------------------------------
#define MMA_16816(c, a, b) \
    asm volatile("mma.sync.aligned.m16n8k16.row.col.f32.f16.f16.f32 " \
        "{%0,%1,%2,%3}, {%4,%5,%6,%7}, {%8,%9}, {%0,%1,%2,%3};" \
        : "+f"((c)[0]), "+f"((c)[1]), "+f"((c)[2]), "+f"((c)[3]) \
        : "r"((a)[0]), "r"((a)[1]), "r"((a)[2]), "r"((a)[3]), \
          "r"((b)[0]), "r"((b)[1]))

// combine (layer 1): outh[n,c] = relu( mean@Wl^T + bl + h@Wr^T ) -> fp16
__global__ __launch_bounds__(256)
void combine_tc(const __half* __restrict__ mean, const __half* __restrict__ h,
                const __half* __restrict__ Wl, const float* __restrict__ bl,
                const __half* __restrict__ Wr, __half* __restrict__ outh) {
    constexpr int BM = 128, BN = 128, BK = 64, LD = 72;
    __shared__ __half As[BM][LD];
    __shared__ __half Bs[BN][LD];

    const int tid = threadIdx.x, wid = tid >> 5, lane = tid & 31;
    const int m0 = blockIdx.x * BM;
    const int wm = (wid & 3) * 32;
    const int wn = (wid >> 2) * 64;

    float acc[2][8][4];
#pragma unroll
    for (int i = 0; i < 2; i++)
#pragma unroll
        for (int j = 0; j < 8; j++)
#pragma unroll
            for (int d = 0; d < 4; d++) acc[i][j][d] = 0.f;

#pragma unroll
    for (int phase = 0; phase < 2; phase++) {
        const __half* A = phase ? h  : mean;
        const __half* B = phase ? Wr : Wl;
#pragma unroll
        for (int kc = 0; kc < CDIM; kc += BK) {
            __syncthreads();
#pragma unroll
            for (int s = tid; s < BM * BK / 8; s += 256) {
                int m = s >> 3, kg = (s & 7) * 8;
                uint4 v = make_uint4(0, 0, 0, 0);
                int node = m0 + m;
                if (node < NNODES)
                    v = *(const uint4*)(A + (size_t)node * CDIM + kc + kg);
                *(uint4*)&As[m][kg] = v;
            }
#pragma unroll
            for (int s = tid; s < BN * BK / 8; s += 256) {
                int c = s >> 3, kg = (s & 7) * 8;
                *(uint4*)&Bs[c][kg] = *(const uint4*)(B + (size_t)c * CDIM + kc + kg);
            }
            __syncthreads();

#pragma unroll
            for (int ks = 0; ks < 4; ks++) {
                int k0 = ks * 16;
                unsigned a[2][4];
#pragma unroll
                for (int mf = 0; mf < 2; mf++) {
                    int row = wm + mf * 16 + (lane & 15);
                    int col = k0 + ((lane >> 4) << 3);
                    unsigned addr = (unsigned)__cvta_generic_to_shared(&As[row][col]);
                    asm volatile("ldmatrix.sync.aligned.m8n8.x4.shared.b16 {%0,%1,%2,%3}, [%4];"
                        : "=r"(a[mf][0]), "=r"(a[mf][1]), "=r"(a[mf][2]), "=r"(a[mf][3])
                        : "r"(addr));
                }
#pragma unroll
                for (int nf = 0; nf < 8; nf++) {
                    int l = lane & 15;
                    int rown = wn + nf * 8 + (l & 7);
                    int col = k0 + ((l >> 3) << 3);
                    unsigned addr = (unsigned)__cvta_generic_to_shared(&Bs[rown][col]);
                    unsigned b[2];
                    asm volatile("ldmatrix.sync.aligned.m8n8.x2.shared.b16 {%0,%1}, [%2];"
                        : "=r"(b[0]), "=r"(b[1]) : "r"(addr));
                    MMA_16816(acc[0][nf], a[0], b);
                    MMA_16816(acc[1][nf], a[1], b);
                }
            }
        }
    }

    const int tg = lane >> 2;
    const int tc = (lane & 3) * 2;
#pragma unroll
    for (int mf = 0; mf < 2; mf++) {
#pragma unroll
        for (int nf = 0; nf < 8; nf++) {
            int n_ = wn + nf * 8 + tc;
            float b0 = bl[n_], b1 = bl[n_ + 1];
            int mA = m0 + wm + mf * 16 + tg;
            int mB = mA + 8;
            if (mA < NNODES) {
                __half2 hv = __float22half2_rn(make_float2(
                    fmaxf(acc[mf][nf][0] + b0, 0.f), fmaxf(acc[mf][nf][1] + b1, 0.f)));
                *(__half2*)(outh + (size_t)mA * BN + n_) = hv;
            }
            if (mB < NNODES) {
                __half2 hv = __float22half2_rn(make_float2(
                    fmaxf(acc[mf][nf][2] + b0, 0.f), fmaxf(acc[mf][nf][3] + b1, 0.f)));
                *(__half2*)(outh + (size_t)mB * BN + n_) = hv;
            }
        }
    }
}

// ---------------------------------------------------------------------------
// FUSED layer-2 combine + layer-3 proj:
//   h2 = relu(mean@Wl2^T + bl2 + h1@Wr2^T)  (fp16, kept in smem tile)
//   th[n,0:64] = h2@Wl3^T (fp16), ts[n,0:64] = h2@Wr3^T (fp32)
#define TILE_LD 136   // 272B rows, 16B-aligned, conflict-free for ldmatrix
#define FUSE_SMEM ((128 * TILE_LD + 128 * 72) * 2)

__global__ __launch_bounds__(256)
void combine_proj_tc(const __half* __restrict__ mean, const __half* __restrict__ h,
                     const __half* __restrict__ Wl2, const float* __restrict__ bl2,
                     const __half* __restrict__ Wr2,
                     const __half* __restrict__ Wl3, const __half* __restrict__ Wr3,
                     __half* __restrict__ th, float* __restrict__ ts) {
    extern __shared__ __half sm[];
    __half (*tile)[TILE_LD] = (__half(*)[TILE_LD])sm;            // 128 x 136
    __half (*Bs)[72]        = (__half(*)[72])(sm + 128 * TILE_LD);

    const int tid = threadIdx.x, wid = tid >> 5, lane = tid & 31;
    const int m0 = blockIdx.x * 128;
    const int wm = (wid & 3) * 32;
    const int wn = (wid >> 2) * 64;
    const int tg = lane >> 2;
    const int tc = (lane & 3) * 2;

    float acc[2][8][4];
#pragma unroll
    for (int i = 0; i < 2; i++)
#pragma unroll
        for (int j = 0; j < 8; j++)
#pragma unroll
            for (int d = 0; d < 4; d++) acc[i][j][d] = 0.f;

    // ---- stage 1: layer-2 combine (tile cols 0..63 per chunk) ----
#pragma unroll
    for (int phase = 0; phase < 2; phase++) {
        const __half* A = phase ? h   : mean;
        const __half* B = phase ? Wr2 : Wl2;
#pragma unroll
        for (int kc = 0; kc < CDIM; kc += 64) {
            __syncthreads();
#pragma unroll
            for (int s = tid; s < 128 * 8; s += 256) {
                int m = s >> 3, kg = (s & 7) * 8;
                uint4 v = make_uint4(0, 0, 0, 0);
                int node = m0 + m;
                if (node < NNODES)
                    v = *(const uint4*)(A + (size_t)node * CDIM + kc + kg);
                *(uint4*)&tile[m][kg] = v;
            }
#pragma unroll
            for (int s = tid; s < 128 * 8; s += 256) {
                int c = s >> 3, kg = (s & 7) * 8;
                *(uint4*)&Bs[c][kg] = *(const uint4*)(B + (size_t)c * CDIM + kc + kg);
            }
            __syncthreads();
#pragma unroll
            for (int ks = 0; ks < 4; ks++) {
                int k0 = ks * 16;
                unsigned a[2][4];
#pragma unroll
                for (int mf = 0; mf < 2; mf++) {
                    int row = wm + mf * 16 + (lane & 15);
                    int col = k0 + ((lane >> 4) << 3);
                    unsigned addr = (unsigned)__cvta_generic_to_shared(&tile[row][col]);
                    asm volatile("ldmatrix.sync.aligned.m8n8.x4.shared.b16 {%0,%1,%2,%3}, [%4];"
                        : "=r"(a[mf][0]), "=r"(a[mf][1]), "=r"(a[mf][2]), "=r"(a[mf][3])
                        : "r"(addr));
                }
#pragma unroll
                for (int nf = 0; nf < 8; nf++) {
                    int l = lane & 15;
                    int rown = wn + nf * 8 + (l & 7);
                    int col = k0 + ((l >> 3) << 3);
                    unsigned addr = (unsigned)__cvta_generic_to_shared(&Bs[rown][col]);
                    unsigned b[2];
                    asm volatile("ldmatrix.sync.aligned.m8n8.x2.shared.b16 {%0,%1}, [%2];"
                        : "=r"(b[0]), "=r"(b[1]) : "r"(addr));
                    MMA_16816(acc[0][nf], a[0], b);
                    MMA_16816(acc[1][nf], a[1], b);
                }
            }
        }
    }

    // ---- epilogue 1: h2 = relu(acc + bias) -> fp16 into tile (full 128 cols) ----
    __syncthreads();   // all stage-1 ldmatrix reads complete
#pragma unroll
    for (int mf = 0; mf < 2; mf++) {
#pragma unroll
        for (int nf = 0; nf < 8; nf++) {
            int n_ = wn + nf * 8 + tc;
            float b0 = bl2[n_], b1 = bl2[n_ + 1];
            int rA = wm + mf * 16 + tg;
            __half2 hv0 = __float22half2_rn(make_float2(
                fmaxf(acc[mf][nf][0] + b0, 0.f), fmaxf(acc[mf][nf][1] + b1, 0.f)));
            __half2 hv1 = __float22half2_rn(make_float2(
                fmaxf(acc[mf][nf][2] + b0, 0.f), fmaxf(acc[mf][nf][3] + b1, 0.f)));
            *(__half2*)&tile[rA][n_]     = hv0;
            *(__half2*)&tile[rA + 8][n_] = hv1;
        }
    }
    __syncthreads();   // tile fully written before proj reads

    // ---- stage 2: proj GEMM over the h2 tile (K = 128) ----
#pragma unroll
    for (int i = 0; i < 2; i++)
#pragma unroll
        for (int j = 0; j < 8; j++)
#pragma unroll
            for (int d = 0; d < 4; d++) acc[i][j][d] = 0.f;

#pragma unroll
    for (int kc = 0; kc < CDIM; kc += 64) {
        if (kc > 0) __syncthreads();
#pragma unroll
        for (int s = tid; s < 128 * 8; s += 256) {
            int c = s >> 3, kg = (s & 7) * 8;
            const __half* w = (c < 64) ? (Wl3 + (size_t)c * CDIM)
                                       : (Wr3 + (size_t)(c - 64) * CDIM);
            *(uint4*)&Bs[c][kg] = *(const uint4*)(w + kc + kg);
        }
        __syncthreads();
#pragma unroll
        for (int ks = 0; ks < 4; ks++) {
            int k0 = ks * 16;
            unsigned a[2][4];
#pragma unroll
            for (int mf = 0; mf < 2; mf++) {
                int row = wm + mf * 16 + (lane & 15);
                int col = kc + k0 + ((lane >> 4) << 3);
                unsigned addr = (unsigned)__cvta_generic_to_shared(&tile[row][col]);
                asm volatile("ldmatrix.sync.aligned.m8n8.x4.shared.b16 {%0,%1,%2,%3}, [%4];"
                    : "=r"(a[mf][0]), "=r"(a[mf][1]), "=r"(a[mf][2]), "=r"(a[mf][3])
                    : "r"(addr));
            }
#pragma unroll
            for (int nf = 0; nf < 8; nf++) {
                int l = lane & 15;
                int rown = wn + nf * 8 + (l & 7);
                int col = k0 + ((l >> 3) << 3);
                unsigned addr = (unsigned)__cvta_generic_to_shared(&Bs[rown][col]);
                unsigned b[2];
                asm volatile("ldmatrix.sync.aligned.m8n8.x2.shared.b16 {%0,%1}, [%2];"
                    : "=r"(b[0]), "=r"(b[1]) : "r"(addr));
                MMA_16816(acc[0][nf], a[0], b);
                MMA_16816(acc[1][nf], a[1], b);
            }
        }
    }

    // ---- epilogue 2: th (fp16, cols 0..63) / ts (fp32, cols 64..127) ----
#pragma unroll
    for (int mf = 0; mf < 2; mf++) {
#pragma unroll
        for (int nf = 0; nf < 8; nf++) {
            int n_ = wn + nf * 8 + tc;
            int mA = m0 + wm + mf * 16 + tg;
            int mB = mA + 8;
            if (n_ < 64) {
                if (mA < NNODES)
                    *(__half2*)(th + (size_t)mA * 64 + n_) = __float22half2_rn(
                        make_float2(acc[mf][nf][0], acc[mf][nf][1]));
                if (mB < NNODES)
                    *(__half2*)(th + (size_t)mB * 64 + n_) = __float22half2_rn(
                        make_float2(acc[mf][nf][2], acc[mf][nf][3]));
            } else {
                int c = n_ - 64;
                if (mA < NNODES)
                    *(float2*)(ts + (size_t)mA * 64 + c) =
                        make_float2(acc[mf][nf][0], acc[mf][nf][1]);
                if (mB < NNODES)
                    *(float2*)(ts + (size_t)mB * 64 + c) =
                        make_float2(acc[mf][nf][2], acc[mf][nf][3]);
            }
        }
    }
}

// ---------------------------------------------------------------------------
extern "C" void kernel_launch(void* const* d_in, const int* in_sizes, int n_in,
                              void* d_out, int out_size) {
    const float* x   = (const float*)d_in[0];
    const int*   ei  = (const int*)d_in[1];      // int32 (JAX x64 disabled)
    const float* Wl1 = (const float*)d_in[2];
    const float* bl1 = (const float*)d_in[3];
    const float* Wr1 = (const float*)d_in[4];
    const float* Wl2 = (const float*)d_in[5];
    const float* bl2 = (const float*)d_in[6];
    const float* Wr2 = (const float*)d_in[7];
    const float* Wl3 = (const float*)d_in[8];
    const float* bl3 = (const float*)d_in[9];
    const float* Wr3 = (const float*)d_in[10];
    float* out = (float*)d_out;

    __half *xh, *aggh, *h1h, *th, *wh;
    float *ts, *inv;
    int *deg, *rowptr, *wcur, *eidx, *bsum;
    cudaGetSymbolAddress((void**)&xh,   g_xh);
    cudaGetSymbolAddress((void**)&aggh, g_aggh);
    cudaGetSymbolAddress((void**)&h1h,  g_h1h);
    cudaGetSymbolAddress((void**)&th,   g_th);
    cudaGetSymbolAddress((void**)&ts,   g_ts);
    cudaGetSymbolAddress((void**)&wh,   g_wh);
    cudaGetSymbolAddress((void**)&inv,  g_inv);
    cudaGetSymbolAddress((void**)&deg,  g_deg);
    cudaGetSymbolAddress((void**)&rowptr, g_rowptr);
    cudaGetSymbolAddress((void**)&wcur, g_wcur);
    cudaGetSymbolAddress((void**)&eidx, g_eidx);
    cudaGetSymbolAddress((void**)&bsum, g_bsum);

    const __half* Wl1h = wh;
    const __half* Wr1h = wh + 16384;
    const __half* Wl2h = wh + 32768;
    const __half* Wr2h = wh + 49152;
    const __half* Wl3h = wh + 65536;
    const __half* Wr3h = wh + 73728;

    cudaFuncSetAttribute(combine_proj_tc,
                         cudaFuncAttributeMaxDynamicSharedMemorySize, FUSE_SMEM);

    const int e8Blocks = (EDGES / 8 + 255) / 256;
    const int aggBlocks = (NNODES * 32 + 255) / 256;   // warp per node
    const int combBlocks = (NNODES + 127) / 128;

    // --- prep (x->fp16 | weights->fp16 | degree hist) + CSR build ---
    cudaMemsetAsync(deg, 0, NNODES * sizeof(int), 0);
    prep_kernel<<<XBLK + WBLK + HBLK, 256>>>(x, xh, Wl1, Wr1, Wl2, Wr2, Wl3, Wr3,
                                             wh, ei, deg);
    partial_kernel<<<NB_SCAN, 256>>>(deg, bsum);
    scanb_kernel<<<1, 512>>>(bsum);
    rescan_kernel<<<NB_SCAN, 256>>>(deg, bsum, rowptr, wcur, inv);
    fill_kernel<<<e8Blocks, 256>>>(ei, wcur, eidx);

    // --- Layer 1: x -> h1h (relu) ---
    aggregate128_kernel<<<aggBlocks, 256>>>(rowptr, eidx, xh, inv, aggh);
    combine_tc<<<combBlocks, 256>>>(aggh, xh, Wl1h, bl1, Wr1h, h1h);

    // --- Layer 2+3 GEMMs fused: h1h -> (th, ts) directly ---
    aggregate128_kernel<<<aggBlocks, 256>>>(rowptr, eidx, h1h, inv, aggh);
    combine_proj_tc<<<combBlocks, 256, FUSE_SMEM>>>(aggh, h1h, Wl2h, bl2, Wr2h,
                                                    Wl3h, Wr3h, th, ts);

    // --- Layer 3 aggregate: mean(th) + ts + bl3 -> out ---
    aggregate_final_kernel<<<aggBlocks, 256>>>(rowptr, eidx, th, ts, bl3, inv, out);
}